// round 8
// baseline (speedup 1.0000x reference)
#include <cuda_runtime.h>
#include <cuda_bf16.h>
#include <stdint.h>
#include <math.h>

#define NB 2
#define BB 4
#define TT 2048
#define DD 128
#define HH 4
#define DK 32
#define ROWS (BB*TT)          // 8192
#define LN_EPS 1e-3f
#define SMEM_GEMM (2*128*68*4 + 256*4)   // W hi/lo tiles + LN reduction = 70656 B

// -------------------- scratch (device globals; no allocs allowed) ------------
__device__ float g_hn [ROWS*DD];
__device__ float g_v  [ROWS*DD];
__device__ float g_ctx[ROWS*DD];
__device__ float g_tmp[ROWS*DD];
__device__ float g_pe [TT*DD];
// split Q/K: [bh=16][t=2048][dp=16] = ROWS*64 words each
__device__ uint32_t g_qh[ROWS*64], g_ql[ROWS*64];
__device__ uint32_t g_kh[ROWS*64], g_kl[ROWS*64];
__device__ uint32_t g_vh[16*32*1024], g_vl[16*32*1024];
__device__ uint32_t g_wh[6*NB*8192], g_wl[6*NB*8192];

// -------------------- split-bf16 helpers ---------------------------------------
__device__ __forceinline__ uint32_t pk_bf2(float a, float b) {
    __nv_bfloat162 t = __floats2bfloat162_rn(a, b);
    return *reinterpret_cast<uint32_t*>(&t);
}
__device__ __forceinline__ void split2(float a, float b, uint32_t& h, uint32_t& l) {
    float ah = __bfloat162float(__float2bfloat16(a));
    float bh = __bfloat162float(__float2bfloat16(b));
    h = pk_bf2(ah, bh);
    l = pk_bf2(a - ah, b - bh);
}
__device__ __forceinline__ void mma16816(float c[4], const uint32_t a[4], const uint32_t b[2]) {
    asm volatile(
        "mma.sync.aligned.m16n8k16.row.col.f32.bf16.bf16.f32 "
        "{%0,%1,%2,%3}, {%4,%5,%6,%7}, {%8,%9}, {%0,%1,%2,%3};\n"
        : "+f"(c[0]), "+f"(c[1]), "+f"(c[2]), "+f"(c[3])
        : "r"(a[0]), "r"(a[1]), "r"(a[2]), "r"(a[3]), "r"(b[0]), "r"(b[1]));
}

// -------------------- positional encoding -------------------------------------
__global__ void pe_kernel(float* __restrict__ pe) {
    int i = blockIdx.x;
    double f = exp(-((double)(2 * i) / 128.0) * 9.210340371976184);
    const double TWO_PI = 6.283185307179586;
    const double INV_TWO_PI = 0.15915494309189535;
    for (int t = threadIdx.x; t < TT; t += blockDim.x) {
        double ang = (double)t * f;
        double r = ang - TWO_PI * floor(ang * INV_TWO_PI);
        float rf = (float)r;
        pe[t * DD + i] = (i & 1) ? cosf(rf) : sinf(rf);
    }
}

// -------------------- fused addpos + first LayerNorm ---------------------------
__global__ void addpos_ln_kernel(const float* __restrict__ in, const float* __restrict__ pe,
                                 const float* __restrict__ g, const float* __restrict__ b,
                                 float* __restrict__ y) {
    int row  = blockIdx.x * 8 + (threadIdx.x >> 5);
    int lane = threadIdx.x & 31;
    int t = row & (TT - 1);
    float4 xv = ((const float4*)in)[row * 32 + lane];
    float4 pv = ((const float4*)pe)[t * 32 + lane];
    xv.x += pv.x; xv.y += pv.y; xv.z += pv.z; xv.w += pv.w;
    float s = xv.x + xv.y + xv.z + xv.w;
    #pragma unroll
    for (int o = 16; o > 0; o >>= 1) s += __shfl_xor_sync(0xffffffff, s, o);
    float mu = s * (1.0f / 128.0f);
    float dx0 = xv.x - mu, dx1 = xv.y - mu, dx2 = xv.z - mu, dx3 = xv.w - mu;
    float sq = dx0*dx0 + dx1*dx1 + dx2*dx2 + dx3*dx3;
    #pragma unroll
    for (int o = 16; o > 0; o >>= 1) sq += __shfl_xor_sync(0xffffffff, sq, o);
    float var = sq * (1.0f / 128.0f);
    float r = rsqrtf(var + LN_EPS);
    float4 gv = ((const float4*)g)[lane];
    float4 bv = ((const float4*)b)[lane];
    float4 ov;
    ov.x = gv.x * dx0 * r + bv.x;
    ov.y = gv.y * dx1 * r + bv.y;
    ov.z = gv.z * dx2 * r + bv.z;
    ov.w = gv.w * dx3 * r + bv.w;
    ((float4*)y)[row * 32 + lane] = ov;
}

// -------------------- weight pre-split ------------------------------------------
__global__ void wsplit_kernel(const float* __restrict__ Wq, const float* __restrict__ Wk,
                              const float* __restrict__ Wv, const float* __restrict__ Wo,
                              const float* __restrict__ W1, const float* __restrict__ W2,
                              uint32_t* __restrict__ wh, uint32_t* __restrict__ wl) {
    const float* Ws[6] = {Wq, Wk, Wv, Wo, W1, W2};
    int fam = blockIdx.y;
    const float* W = Ws[fam];
    int idx = blockIdx.x * 256 + threadIdx.x;   // 0..16383 = NB*8192
    int layer = idx >> 13;
    int rem = idx & 8191;
    int kp = rem >> 7, n = rem & 127;
    const float* Wm = W + layer * 128 * 128;
    float w0 = Wm[(2 * kp) * 128 + n];
    float w1 = Wm[(2 * kp + 1) * 128 + n];
    uint32_t hi, lo;
    split2(w0, w1, hi, lo);
    int out = (fam * NB + layer) * 8192 + n * 64 + kp;
    wh[out] = hi;
    wl[out] = lo;
}

// -------------------- V transpose/split -----------------------------------------
__global__ void vprep_kernel(const float* __restrict__ v,
                             uint32_t* __restrict__ vh, uint32_t* __restrict__ vl) {
    int bh = blockIdx.x >> 5;
    int kp0 = (blockIdx.x & 31) * 32;
    const float* vb = v + (size_t)bh * 2048 * 32;
    uint32_t* th = vh + (size_t)bh * 32 * 1024;
    uint32_t* tl = vl + (size_t)bh * 32 * 1024;
    #pragma unroll
    for (int i = 0; i < 4; i++) {
        int idx = threadIdx.x + i * 256;   // 0..1023
        int d = idx >> 5;
        int kpl = idx & 31;
        float v0 = vb[(size_t)(2 * (kp0 + kpl)) * 32 + d];
        float v1 = vb[(size_t)(2 * (kp0 + kpl) + 1) * 32 + d];
        uint32_t hi, lo;
        split2(v0, v1, hi, lo);
        th[d * 1024 + kp0 + kpl] = hi;
        tl[d * 1024 + kp0 + kpl] = lo;
    }
}

// -------------------- tensor-core GEMM body (M=32, N=128, 8 warps) ---------------
// warp w: row-group rg=w>>2 (rows m0+rg*16+lq, +8), col-group cg=w&3 (cols cg*32+nt*8)
// MODE: 1 relu->C, 3 fp32 scatter [B,H,T,DK]->C, 4 split d-pair (scaled)->Ch/Cl,
//       5 LN(acc+bias)->C, 6 LN(acc+bias+R)->C
template <int MODE>
__device__ __forceinline__ void gemm_body(
        uint32_t (*Wh)[68], uint32_t (*Wl)[68],
        float (*ssum)[4], float (*ssq)[4],
        const float* __restrict__ A,
        const uint32_t* __restrict__ Wph, const uint32_t* __restrict__ Wpl,
        const float* __restrict__ bias, const float* __restrict__ R,
        const float* __restrict__ lng, const float* __restrict__ lnb,
        float* __restrict__ C, uint32_t* __restrict__ Ch, uint32_t* __restrict__ Cl,
        float scl, int m0) {
    int tid = threadIdx.x;
    int w = tid >> 5, lane = tid & 31;
    int lq = lane >> 2, lr = lane & 3;
    int rg = w >> 2, cg = w & 3;

    // stage pre-split W tile: 128 n-rows x 64 kp, hi + lo (uint4 copies)
    #pragma unroll
    for (int i = 0; i < 8; i++) {
        int idx = tid + i * 256;            // 0..2047 uint4s
        int n = idx >> 4, u4 = (idx & 15) * 4;
        *(uint4*)&Wh[n][u4] = *(const uint4*)&Wph[(size_t)n * 64 + u4];
    }
    #pragma unroll
    for (int i = 0; i < 8; i++) {
        int idx = tid + i * 256;
        int n = idx >> 4, u4 = (idx & 15) * 4;
        *(uint4*)&Wl[n][u4] = *(const uint4*)&Wpl[(size_t)n * 64 + u4];
    }

    int mrow = m0 + rg * 16 + lq;
    const float* Ar0 = &A[(size_t)mrow * 128];
    const float* Ar8 = Ar0 + 8 * 128;
    float acc[4][4] = {};

    float2 af[4];
    af[0] = *(const float2*)&Ar0[2 * lr];
    af[1] = *(const float2*)&Ar8[2 * lr];
    af[2] = *(const float2*)&Ar0[2 * lr + 8];
    af[3] = *(const float2*)&Ar8[2 * lr + 8];
    __syncthreads();

    #pragma unroll
    for (int kc = 0; kc < 8; kc++) {
        uint32_t ah[4], al[4];
        #pragma unroll
        for (int r = 0; r < 4; r++) split2(af[r].x, af[r].y, ah[r], al[r]);
        float2 af2[4];
        if (kc < 7) {
            int ko = (kc + 1) * 16;
            af2[0] = *(const float2*)&Ar0[ko + 2 * lr];
            af2[1] = *(const float2*)&Ar8[ko + 2 * lr];
            af2[2] = *(const float2*)&Ar0[ko + 2 * lr + 8];
            af2[3] = *(const float2*)&Ar8[ko + 2 * lr + 8];
        }
        #pragma unroll
        for (int nt = 0; nt < 4; nt++) {
            int n = cg * 32 + nt * 8 + lq;
            const uint32_t* ph = &Wh[n][kc * 8 + lr];
            const uint32_t* pl = &Wl[n][kc * 8 + lr];
            uint32_t bh2[2] = { ph[0], ph[4] };
            uint32_t bl2[2] = { pl[0], pl[4] };
            mma16816(acc[nt], ah, bh2);
            mma16816(acc[nt], ah, bl2);
            mma16816(acc[nt], al, bh2);
        }
        if (kc < 7) {
            af[0] = af2[0]; af[1] = af2[1]; af[2] = af2[2]; af[3] = af2[3];
        }
    }

    if (MODE == 5 || MODE == 6) {
        float xs[4][4];
        #pragma unroll
        for (int nt = 0; nt < 4; nt++) {
            int n = cg * 32 + nt * 8 + 2 * lr;
            float2 bv = *(const float2*)&bias[n];
            xs[nt][0] = acc[nt][0] + bv.x;
            xs[nt][1] = acc[nt][1] + bv.y;
            xs[nt][2] = acc[nt][2] + bv.x;
            xs[nt][3] = acc[nt][3] + bv.y;
            if (MODE == 6) {
                float2 r0 = *(const float2*)&R[(size_t)mrow * 128 + n];
                float2 r1 = *(const float2*)&R[(size_t)(mrow + 8) * 128 + n];
                xs[nt][0] += r0.x; xs[nt][1] += r0.y;
                xs[nt][2] += r1.x; xs[nt][3] += r1.y;
            }
        }
        float sA = 0, qA = 0, sB = 0, qB = 0;
        #pragma unroll
        for (int nt = 0; nt < 4; nt++) {
            sA += xs[nt][0] + xs[nt][1];
            qA += xs[nt][0]*xs[nt][0] + xs[nt][1]*xs[nt][1];
            sB += xs[nt][2] + xs[nt][3];
            qB += xs[nt][2]*xs[nt][2] + xs[nt][3]*xs[nt][3];
        }
        #pragma unroll
        for (int o2 = 1; o2 < 4; o2 <<= 1) {
            sA += __shfl_xor_sync(0xffffffff, sA, o2);
            qA += __shfl_xor_sync(0xffffffff, qA, o2);
            sB += __shfl_xor_sync(0xffffffff, sB, o2);
            qB += __shfl_xor_sync(0xffffffff, qB, o2);
        }
        int ra = rg * 16 + lq, rb = ra + 8;
        if (lr == 0) {
            ssum[ra][cg] = sA; ssq[ra][cg] = qA;
            ssum[rb][cg] = sB; ssq[rb][cg] = qB;
        }
        __syncthreads();
        float fsA = ssum[ra][0] + ssum[ra][1] + ssum[ra][2] + ssum[ra][3];
        float fqA = ssq[ra][0] + ssq[ra][1] + ssq[ra][2] + ssq[ra][3];
        float fsB = ssum[rb][0] + ssum[rb][1] + ssum[rb][2] + ssum[rb][3];
        float fqB = ssq[rb][0] + ssq[rb][1] + ssq[rb][2] + ssq[rb][3];
        float muA = fsA * (1.0f / 128.0f);
        float muB = fsB * (1.0f / 128.0f);
        float rA = rsqrtf(fqA * (1.0f / 128.0f) - muA * muA + LN_EPS);
        float rB = rsqrtf(fqB * (1.0f / 128.0f) - muB * muB + LN_EPS);
        #pragma unroll
        for (int nt = 0; nt < 4; nt++) {
            int n = cg * 32 + nt * 8 + 2 * lr;
            float2 gv  = *(const float2*)&lng[n];
            float2 bv2 = *(const float2*)&lnb[n];
            float2 y0 = { gv.x * (xs[nt][0] - muA) * rA + bv2.x,
                          gv.y * (xs[nt][1] - muA) * rA + bv2.y };
            float2 y1 = { gv.x * (xs[nt][2] - muB) * rB + bv2.x,
                          gv.y * (xs[nt][3] - muB) * rB + bv2.y };
            *(float2*)&C[(size_t)mrow * 128 + n] = y0;
            *(float2*)&C[(size_t)(mrow + 8) * 128 + n] = y1;
        }
        return;
    }

    #pragma unroll
    for (int nt = 0; nt < 4; nt++) {
        int n = cg * 32 + nt * 8 + 2 * lr;
        float2 bv = *(const float2*)&bias[n];
        float2 o0 = { acc[nt][0] + bv.x, acc[nt][1] + bv.y };
        float2 o1 = { acc[nt][2] + bv.x, acc[nt][3] + bv.y };
        if (MODE == 1) {
            o0.x = fmaxf(o0.x, 0.f); o0.y = fmaxf(o0.y, 0.f);
            o1.x = fmaxf(o1.x, 0.f); o1.y = fmaxf(o1.y, 0.f);
            *(float2*)&C[(size_t)mrow * 128 + n] = o0;
            *(float2*)&C[(size_t)(mrow + 8) * 128 + n] = o1;
        }
        if (MODE == 3) {
            int dk = nt * 8 + 2 * lr;
            int b0i = mrow >> 11, t0i = mrow & 2047;
            *(float2*)&C[(((b0i << 2) + cg) * 2048 + t0i) * 32 + dk] = o0;
            int b1i = (mrow + 8) >> 11, t1i = (mrow + 8) & 2047;
            *(float2*)&C[(((b1i << 2) + cg) * 2048 + t1i) * 32 + dk] = o1;
        }
        if (MODE == 4) {
            int dp = nt * 4 + lr;
            int b0i = mrow >> 11, t0i = mrow & 2047;
            uint32_t hi, lo;
            split2(o0.x * scl, o0.y * scl, hi, lo);
            size_t idx0 = ((size_t)((b0i << 2) + cg) * 2048 + t0i) * 16 + dp;
            Ch[idx0] = hi; Cl[idx0] = lo;
            int b1i = (mrow + 8) >> 11, t1i = (mrow + 8) & 2047;
            split2(o1.x * scl, o1.y * scl, hi, lo);
            size_t idx1 = ((size_t)((b1i << 2) + cg) * 2048 + t1i) * 16 + dp;
            Ch[idx1] = hi; Cl[idx1] = lo;
        }
    }
}

template <int MODE>
__global__ __launch_bounds__(256) void gemm_mma_kernel(
        const float* __restrict__ A,
        const uint32_t* __restrict__ Wph, const uint32_t* __restrict__ Wpl,
        const float* __restrict__ bias, const float* __restrict__ R,
        const float* __restrict__ lng, const float* __restrict__ lnb,
        float* __restrict__ C) {
    extern __shared__ uint32_t dyn[];
    uint32_t (*Wh)[68] = (uint32_t(*)[68])dyn;
    uint32_t (*Wl)[68] = (uint32_t(*)[68])(dyn + 128 * 68);
    float (*ssum)[4] = (float(*)[4])(dyn + 2 * 128 * 68);
    float (*ssq)[4]  = (float(*)[4])(dyn + 2 * 128 * 68 + 128);
    gemm_body<MODE>(Wh, Wl, ssum, ssq, A, Wph, Wpl, bias, R, lng, lnb,
                    C, nullptr, nullptr, 1.0f, blockIdx.x * 32);
}

// fused Q/K/V: grid (256, 3).
__global__ __launch_bounds__(256) void qkv_mma_kernel(
        const float* __restrict__ A,
        const uint32_t* __restrict__ Wqh, const uint32_t* __restrict__ Wql, const float* __restrict__ bq,
        const uint32_t* __restrict__ Wkh, const uint32_t* __restrict__ Wkl, const float* __restrict__ bk,
        const uint32_t* __restrict__ Wvh, const uint32_t* __restrict__ Wvl, const float* __restrict__ bv,
        uint32_t* __restrict__ qh, uint32_t* __restrict__ ql,
        uint32_t* __restrict__ kh, uint32_t* __restrict__ kl,
        float* __restrict__ v) {
    extern __shared__ uint32_t dyn[];
    uint32_t (*Wh)[68] = (uint32_t(*)[68])dyn;
    uint32_t (*Wl)[68] = (uint32_t(*)[68])(dyn + 128 * 68);
    float (*ssum)[4] = (float(*)[4])(dyn + 2 * 128 * 68);
    float (*ssq)[4]  = (float(*)[4])(dyn + 2 * 128 * 68 + 128);
    int m0 = blockIdx.x * 32;
    int sel = blockIdx.y;
    const float QSCL = 0.17677669529663687f * 1.4426950408889634f;  // 1/sqrt(32)*log2(e)
    if (sel == 0) {
        gemm_body<4>(Wh, Wl, ssum, ssq, A, Wqh, Wql, bq, nullptr, nullptr, nullptr,
                     nullptr, qh, ql, QSCL, m0);
    } else if (sel == 1) {
        gemm_body<4>(Wh, Wl, ssum, ssq, A, Wkh, Wkl, bk, nullptr, nullptr, nullptr,
                     nullptr, kh, kl, 1.0f, m0);
    } else {
        gemm_body<3>(Wh, Wl, ssum, ssq, A, Wvh, Wvl, bv, nullptr, nullptr, nullptr,
                     v, nullptr, nullptr, 1.0f, m0);
    }
}

// -------------------- flash attention (pre-split inputs, double-buffered) --------
__global__ __launch_bounds__(256) void attn_kernel(
        const uint32_t* __restrict__ Qh, const uint32_t* __restrict__ Ql,
        const uint32_t* __restrict__ Kh, const uint32_t* __restrict__ Kl,
        const uint32_t* __restrict__ Vh, const uint32_t* __restrict__ Vl,
        float* __restrict__ ctx) {
    __shared__ __align__(16) uint32_t Ksh[2][64 * 20];
    __shared__ __align__(16) uint32_t Ksl[2][64 * 20];
    __shared__ __align__(16) uint32_t Vsh[2][32 * 36];
    __shared__ __align__(16) uint32_t Vsl[2][32 * 36];

    int bid = blockIdx.x;
    int bh  = bid >> 4;
    int qc  = bid & 15;
    int q0  = qc * 128;
    int tid = threadIdx.x;
    int w    = tid >> 5;
    int lane = tid & 31;
    int lq   = lane >> 2;
    int lr   = lane & 3;
    int row0 = q0 + w * 16 + lq;

    const uint32_t* QhB = Qh + (size_t)bh * 2048 * 16;
    const uint32_t* QlB = Ql + (size_t)bh * 2048 * 16;
    const uint32_t* KhB = Kh + (size_t)bh * 2048 * 16;
    const uint32_t* KlB = Kl + (size_t)bh * 2048 * 16;
    const uint32_t* VhB = Vh + (size_t)bh * 32 * 1024;
    const uint32_t* VlB = Vl + (size_t)bh * 32 * 1024;

    uint32_t qh[2][4], ql[2][4];
    #pragma unroll
    for (int c2 = 0; c2 < 2; c2++) {
        #pragma unroll
        for (int r = 0; r < 4; r++) {
            int row = row0 + ((r & 1) ? 8 : 0);
            int dp = c2 * 8 + lr + ((r >= 2) ? 4 : 0);
            qh[c2][r] = QhB[(size_t)row * 16 + dp];
            ql[c2][r] = QlB[(size_t)row * 16 + dp];
        }
    }

    float m0 = -1e30f, m1 = -1e30f, l0 = 0.f, l1 = 0.f;
    float o[4][4] = {};

    int kkey = tid >> 2, kdq = (tid & 3) * 4;
    int vd = tid >> 3, vkp = (tid & 7) * 4;
    uint4 kh4, kl4, vh4, vl4;
    kh4 = *(const uint4*)&KhB[kkey * 16 + kdq];
    kl4 = *(const uint4*)&KlB[kkey * 16 + kdq];
    vh4 = *(const uint4*)&VhB[vd * 1024 + vkp];
    vl4 = *(const uint4*)&VlB[vd * 1024 + vkp];

    for (int tile = 0; tile < 32; tile++) {
        int cur = tile & 1;
        *(uint4*)&Ksh[cur][kkey * 20 + kdq] = kh4;
        *(uint4*)&Ksl[cur][kkey * 20 + kdq] = kl4;
        *(uint4*)&Vsh[cur][vd * 36 + vkp] = vh4;
        *(uint4*)&Vsl[cur][vd * 36 + vkp] = vl4;

        if (tile < 31) {
            int t0 = (tile + 1) * 64, kp0 = (tile + 1) * 32;
            kh4 = *(const uint4*)&KhB[(size_t)(t0 + kkey) * 16 + kdq];
            kl4 = *(const uint4*)&KlB[(size_t)(t0 + kkey) * 16 + kdq];
            vh4 = *(const uint4*)&VhB[vd * 1024 + kp0 + vkp];
            vl4 = *(const uint4*)&VlB[vd * 1024 + kp0 + vkp];
        }
        __syncthreads();

        // ---- QK^T (log2 domain; Q pre-scaled) ----
        float c[8][4] = {};
        #pragma unroll
        for (int nt = 0; nt < 8; nt++) {
            int key = nt * 8 + lq;
            const uint32_t* kh = &Ksh[cur][key * 20 + lr];
            const uint32_t* kl = &Ksl[cur][key * 20 + lr];
            #pragma unroll
            for (int kc = 0; kc < 2; kc++) {
                uint32_t bhf[2] = { kh[8 * kc], kh[8 * kc + 4] };
                uint32_t blf[2] = { kl[8 * kc], kl[8 * kc + 4] };
                mma16816(c[nt], qh[kc], bhf);
                mma16816(c[nt], qh[kc], blf);
                mma16816(c[nt], ql[kc], bhf);
            }
        }

        // ---- online softmax (base 2) ----
        float mx0 = -1e30f, mx1 = -1e30f;
        #pragma unroll
        for (int nt = 0; nt < 8; nt++) {
            mx0 = fmaxf(mx0, fmaxf(c[nt][0], c[nt][1]));
            mx1 = fmaxf(mx1, fmaxf(c[nt][2], c[nt][3]));
        }
        mx0 = fmaxf(mx0, __shfl_xor_sync(0xffffffff, mx0, 1));
        mx0 = fmaxf(mx0, __shfl_xor_sync(0xffffffff, mx0, 2));
        mx1 = fmaxf(mx1, __shfl_xor_sync(0xffffffff, mx1, 1));
        mx1 = fmaxf(mx1, __shfl_xor_sync(0xffffffff, mx1, 2));
        float nm0 = fmaxf(m0, mx0), nm1 = fmaxf(m1, mx1);
        float f0 = exp2f(m0 - nm0), f1 = exp2f(m1 - nm1);
        m0 = nm0; m1 = nm1;
        l0 *= f0; l1 *= f1;
        #pragma unroll
        for (int dt = 0; dt < 4; dt++) {
            o[dt][0] *= f0; o[dt][1] *= f0;
            o[dt][2] *= f1; o[dt][3] *= f1;
        }
        #pragma unroll
        for (int nt = 0; nt < 8; nt++) {
            c[nt][0] = exp2f(c[nt][0] - m0);
            c[nt][1] = exp2f(c[nt][1] - m0);
            c[nt][2] = exp2f(c[nt][2] - m1);
            c[nt][3] = exp2f(c[nt][3] - m1);
            l0 += c[nt][0] + c[nt][1];
            l1 += c[nt][2] + c[nt][3];
        }

        // ---- P @ V ----
        #pragma unroll
        for (int kc = 0; kc < 4; kc++) {
            uint32_t ah[4], al[4];
            split2(c[2*kc][0],   c[2*kc][1],   ah[0], al[0]);
            split2(c[2*kc][2],   c[2*kc][3],   ah[1], al[1]);
            split2(c[2*kc+1][0], c[2*kc+1][1], ah[2], al[2]);
            split2(c[2*kc+1][2], c[2*kc+1][3], ah[3], al[3]);
            #pragma unroll
            for (int dt = 0; dt < 4; dt++) {
                int d = dt * 8 + lq;
                const uint32_t* vh = &Vsh[cur][d * 36 + kc * 8 + lr];
                const uint32_t* vl = &Vsl[cur][d * 36 + kc * 8 + lr];
                uint32_t bhf[2] = { vh[0], vh[4] };
                uint32_t blf[2] = { vl[0], vl[4] };
                mma16816(o[dt], ah, bhf);
                mma16816(o[dt], ah, blf);
                mma16816(o[dt], al, bhf);
            }
        }
    }

    // ---- epilogue ----
    l0 += __shfl_xor_sync(0xffffffff, l0, 1);
    l0 += __shfl_xor_sync(0xffffffff, l0, 2);
    l1 += __shfl_xor_sync(0xffffffff, l1, 1);
    l1 += __shfl_xor_sync(0xffffffff, l1, 2);
    float inv0 = 1.0f / l0, inv1 = 1.0f / l1;
    int b = bh >> 2, hh = bh & 3;
    #pragma unroll
    for (int dt = 0; dt < 4; dt++) {
        int d = dt * 8 + 2 * lr;
        float2 v0 = { o[dt][0] * inv0, o[dt][1] * inv0 };
        float2 v1 = { o[dt][2] * inv1, o[dt][3] * inv1 };
        *(float2*)&ctx[(size_t)(b * TT + row0) * 128 + hh * 32 + d]       = v0;
        *(float2*)&ctx[(size_t)(b * TT + row0 + 8) * 128 + hh * 32 + d]   = v1;
    }
}

// -------------------- launch ------------------------------------------------------
extern "C" void kernel_launch(void* const* d_in, const int* in_sizes, int n_in,
                              void* d_out, int out_size) {
    const float* in  = (const float*)d_in[0];
    const float* Wq  = (const float*)d_in[1];
    const float* bq  = (const float*)d_in[2];
    const float* Wk  = (const float*)d_in[3];
    const float* bk  = (const float*)d_in[4];
    const float* Wv  = (const float*)d_in[5];
    const float* bv  = (const float*)d_in[6];
    const float* Wo  = (const float*)d_in[7];
    const float* bo  = (const float*)d_in[8];
    const float* W1  = (const float*)d_in[9];
    const float* b1  = (const float*)d_in[10];
    const float* W2  = (const float*)d_in[11];
    const float* b2  = (const float*)d_in[12];
    const float* lng = (const float*)d_in[13];
    const float* lnb = (const float*)d_in[14];
    float* out = (float*)d_out;

    float *hn, *v, *ctx, *tmp, *pe;
    uint32_t *qh, *ql, *kh, *kl, *vh, *vl, *wh, *wl;
    cudaGetSymbolAddress((void**)&hn,  g_hn);
    cudaGetSymbolAddress((void**)&v,   g_v);
    cudaGetSymbolAddress((void**)&ctx, g_ctx);
    cudaGetSymbolAddress((void**)&tmp, g_tmp);
    cudaGetSymbolAddress((void**)&pe,  g_pe);
    cudaGetSymbolAddress((void**)&qh,  g_qh);
    cudaGetSymbolAddress((void**)&ql,  g_ql);
    cudaGetSymbolAddress((void**)&kh,  g_kh);
    cudaGetSymbolAddress((void**)&kl,  g_kl);
    cudaGetSymbolAddress((void**)&vh,  g_vh);
    cudaGetSymbolAddress((void**)&vl,  g_vl);
    cudaGetSymbolAddress((void**)&wh,  g_wh);
    cudaGetSymbolAddress((void**)&wl,  g_wl);

    cudaFuncSetAttribute(gemm_mma_kernel<1>, cudaFuncAttributeMaxDynamicSharedMemorySize, SMEM_GEMM);
    cudaFuncSetAttribute(gemm_mma_kernel<5>, cudaFuncAttributeMaxDynamicSharedMemorySize, SMEM_GEMM);
    cudaFuncSetAttribute(gemm_mma_kernel<6>, cudaFuncAttributeMaxDynamicSharedMemorySize, SMEM_GEMM);
    cudaFuncSetAttribute(qkv_mma_kernel, cudaFuncAttributeMaxDynamicSharedMemorySize, SMEM_GEMM);

    pe_kernel<<<128, 256>>>(pe);
    wsplit_kernel<<<dim3(64, 6), 256>>>(Wq, Wk, Wv, Wo, W1, W2, wh, wl);
    addpos_ln_kernel<<<ROWS / 8, 256>>>(in, pe, lng, lnb, hn);

    for (int i = 0; i < NB; i++) {
        const uint32_t* Wqh = wh + (0 * NB + i) * 8192; const uint32_t* Wql = wl + (0 * NB + i) * 8192;
        const uint32_t* Wkh = wh + (1 * NB + i) * 8192; const uint32_t* Wkl = wl + (1 * NB + i) * 8192;
        const uint32_t* Wvh = wh + (2 * NB + i) * 8192; const uint32_t* Wvl = wl + (2 * NB + i) * 8192;
        const uint32_t* Woh = wh + (3 * NB + i) * 8192; const uint32_t* Wol = wl + (3 * NB + i) * 8192;
        const uint32_t* W1h = wh + (4 * NB + i) * 8192; const uint32_t* W1l = wl + (4 * NB + i) * 8192;
        const uint32_t* W2h = wh + (5 * NB + i) * 8192; const uint32_t* W2l = wl + (5 * NB + i) * 8192;
        const float* bqi = bq + i * DD;
        const float* bki = bk + i * DD;
        const float* bvi = bv + i * DD;
        const float* boi = bo + i * DD;
        const float* b1i = b1 + i * DD;
        const float* b2i = b2 + i * DD;

        qkv_mma_kernel<<<dim3(256, 3), 256, SMEM_GEMM>>>(hn, Wqh, Wql, bqi, Wkh, Wkl, bki,
                                                         Wvh, Wvl, bvi, qh, ql, kh, kl, v);
        vprep_kernel<<<512, 256>>>(v, vh, vl);
        attn_kernel<<<256, 256>>>(qh, ql, kh, kl, vh, vl, ctx);
        // Wo GEMM fused with pre-FFN LayerNorm -> hn
        gemm_mma_kernel<5><<<256, 256, SMEM_GEMM>>>(ctx, Woh, Wol, boi, nullptr,
                                                    lng + (2 * i + 1) * DD, lnb + (2 * i + 1) * DD, hn);
        // FFN inner (relu) -> tmp
        gemm_mma_kernel<1><<<256, 256, SMEM_GEMM>>>(hn, W1h, W1l, b1i, nullptr,
                                                    nullptr, nullptr, tmp);
        // FFN outer + residual + next LayerNorm -> hn (or final LN -> out)
        const float* gN = (i == NB - 1) ? (lng + 3 * DD) : (lng + (2 * i + 2) * DD);
        const float* bN = (i == NB - 1) ? (lnb + 3 * DD) : (lnb + (2 * i + 2) * DD);
        float* dstN = (i == NB - 1) ? out : hn;
        gemm_mma_kernel<6><<<256, 256, SMEM_GEMM>>>(tmp, W2h, W2l, b2i, hn, gN, bN, dstN);
    }
}

// round 9
// speedup vs baseline: 1.0048x; 1.0048x over previous
#include <cuda_runtime.h>
#include <cuda_bf16.h>
#include <stdint.h>
#include <math.h>

#define NB 2
#define BB 4
#define TT 2048
#define DD 128
#define HH 4
#define DK 32
#define ROWS (BB*TT)          // 8192
#define LN_EPS 1e-3f
#define SMEM_GEMM (2*128*68*4 + 256*4)   // W hi/lo tiles + LN reduction = 70656 B

// -------------------- scratch (device globals; no allocs allowed) ------------
__device__ float g_v  [ROWS*DD];
__device__ float g_pe [TT*DD];
// split activations, fragment-major widx layout: [row][64]
__device__ uint32_t g_hnh [ROWS*64], g_hnl [ROWS*64];
__device__ uint32_t g_tmph[ROWS*64], g_tmpl[ROWS*64];
__device__ uint32_t g_ctxh[ROWS*64], g_ctxl[ROWS*64];
// split Q/K: [bh=16][t=2048][dp=16] linear dp
__device__ uint32_t g_qh[ROWS*64], g_ql[ROWS*64];
__device__ uint32_t g_kh[ROWS*64], g_kl[ROWS*64];
__device__ uint32_t g_vh[16*32*1024], g_vl[16*32*1024];
__device__ uint32_t g_wh[6*NB*8192], g_wl[6*NB*8192];

// -------------------- split-bf16 helpers ---------------------------------------
__device__ __forceinline__ uint32_t pk_bf2(float a, float b) {
    __nv_bfloat162 t = __floats2bfloat162_rn(a, b);
    return *reinterpret_cast<uint32_t*>(&t);
}
__device__ __forceinline__ void split2(float a, float b, uint32_t& h, uint32_t& l) {
    float ah = __bfloat162float(__float2bfloat16(a));
    float bh = __bfloat162float(__float2bfloat16(b));
    h = pk_bf2(ah, bh);
    l = pk_bf2(a - ah, b - bh);
}
__device__ __forceinline__ float2 unsplit(uint32_t h, uint32_t l) {
    __nv_bfloat162 hb = *reinterpret_cast<__nv_bfloat162*>(&h);
    __nv_bfloat162 lb = *reinterpret_cast<__nv_bfloat162*>(&l);
    return make_float2(__bfloat162float(hb.x) + __bfloat162float(lb.x),
                       __bfloat162float(hb.y) + __bfloat162float(lb.y));
}
// fragment-major permutation: pairs (dp, dp+4 within the 8-dp kc group) adjacent
__device__ __forceinline__ int widx(int dp) {
    return (dp & ~7) + 2 * (dp & 3) + ((dp >> 2) & 1);
}
__device__ __forceinline__ void mma16816(float c[4], const uint32_t a[4], const uint32_t b[2]) {
    asm volatile(
        "mma.sync.aligned.m16n8k16.row.col.f32.bf16.bf16.f32 "
        "{%0,%1,%2,%3}, {%4,%5,%6,%7}, {%8,%9}, {%0,%1,%2,%3};\n"
        : "+f"(c[0]), "+f"(c[1]), "+f"(c[2]), "+f"(c[3])
        : "r"(a[0]), "r"(a[1]), "r"(a[2]), "r"(a[3]), "r"(b[0]), "r"(b[1]));
}

// -------------------- positional encoding -------------------------------------
__global__ void pe_kernel(float* __restrict__ pe) {
    int i = blockIdx.x;
    double f = exp(-((double)(2 * i) / 128.0) * 9.210340371976184);
    const double TWO_PI = 6.283185307179586;
    const double INV_TWO_PI = 0.15915494309189535;
    for (int t = threadIdx.x; t < TT; t += blockDim.x) {
        double ang = (double)t * f;
        double r = ang - TWO_PI * floor(ang * INV_TWO_PI);
        float rf = (float)r;
        pe[t * DD + i] = (i & 1) ? cosf(rf) : sinf(rf);
    }
}

// -------------------- fused addpos + first LayerNorm -> split hn -----------------
__global__ void addpos_ln_kernel(const float* __restrict__ in, const float* __restrict__ pe,
                                 const float* __restrict__ g, const float* __restrict__ b,
                                 uint32_t* __restrict__ Ch, uint32_t* __restrict__ Cl) {
    int row  = blockIdx.x * 8 + (threadIdx.x >> 5);
    int lane = threadIdx.x & 31;
    int t = row & (TT - 1);
    float4 xv = ((const float4*)in)[row * 32 + lane];
    float4 pv = ((const float4*)pe)[t * 32 + lane];
    xv.x += pv.x; xv.y += pv.y; xv.z += pv.z; xv.w += pv.w;
    float s = xv.x + xv.y + xv.z + xv.w;
    #pragma unroll
    for (int o = 16; o > 0; o >>= 1) s += __shfl_xor_sync(0xffffffff, s, o);
    float mu = s * (1.0f / 128.0f);
    float dx0 = xv.x - mu, dx1 = xv.y - mu, dx2 = xv.z - mu, dx3 = xv.w - mu;
    float sq = dx0*dx0 + dx1*dx1 + dx2*dx2 + dx3*dx3;
    #pragma unroll
    for (int o = 16; o > 0; o >>= 1) sq += __shfl_xor_sync(0xffffffff, sq, o);
    float var = sq * (1.0f / 128.0f);
    float r = rsqrtf(var + LN_EPS);
    float4 gv = ((const float4*)g)[lane];
    float4 bv = ((const float4*)b)[lane];
    float y0 = gv.x * dx0 * r + bv.x;
    float y1 = gv.y * dx1 * r + bv.y;
    float y2 = gv.z * dx2 * r + bv.z;
    float y3 = gv.w * dx3 * r + bv.w;
    uint32_t h0, l0, h1, l1;
    split2(y0, y1, h0, l0);
    split2(y2, y3, h1, l1);
    int base = row * 64;
    Ch[base + widx(2 * lane)]     = h0; Cl[base + widx(2 * lane)]     = l0;
    Ch[base + widx(2 * lane + 1)] = h1; Cl[base + widx(2 * lane + 1)] = l1;
}

// -------------------- weight pre-split ------------------------------------------
__global__ void wsplit_kernel(const float* __restrict__ Wq, const float* __restrict__ Wk,
                              const float* __restrict__ Wv, const float* __restrict__ Wo,
                              const float* __restrict__ W1, const float* __restrict__ W2,
                              uint32_t* __restrict__ wh, uint32_t* __restrict__ wl) {
    const float* Ws[6] = {Wq, Wk, Wv, Wo, W1, W2};
    int fam = blockIdx.y;
    const float* W = Ws[fam];
    int idx = blockIdx.x * 256 + threadIdx.x;   // 0..16383 = NB*8192
    int layer = idx >> 13;
    int rem = idx & 8191;
    int kp = rem >> 7, n = rem & 127;
    const float* Wm = W + layer * 128 * 128;
    float w0 = Wm[(2 * kp) * 128 + n];
    float w1 = Wm[(2 * kp + 1) * 128 + n];
    uint32_t hi, lo;
    split2(w0, w1, hi, lo);
    int out = (fam * NB + layer) * 8192 + n * 64 + kp;
    wh[out] = hi;
    wl[out] = lo;
}

// -------------------- V transpose/split -----------------------------------------
__global__ void vprep_kernel(const float* __restrict__ v,
                             uint32_t* __restrict__ vh, uint32_t* __restrict__ vl) {
    int bh = blockIdx.x >> 5;
    int kp0 = (blockIdx.x & 31) * 32;
    const float* vb = v + (size_t)bh * 2048 * 32;
    uint32_t* th = vh + (size_t)bh * 32 * 1024;
    uint32_t* tl = vl + (size_t)bh * 32 * 1024;
    #pragma unroll
    for (int i = 0; i < 4; i++) {
        int idx = threadIdx.x + i * 256;   // 0..1023
        int d = idx >> 5;
        int kpl = idx & 31;
        float v0 = vb[(size_t)(2 * (kp0 + kpl)) * 32 + d];
        float v1 = vb[(size_t)(2 * (kp0 + kpl) + 1) * 32 + d];
        uint32_t hi, lo;
        split2(v0, v1, hi, lo);
        th[d * 1024 + kp0 + kpl] = hi;
        tl[d * 1024 + kp0 + kpl] = lo;
    }
}

// -------------------- tensor-core GEMM body (M=32, N=128, 8 warps) ---------------
// A pre-split (widx layout). warp w: rg=w>>2 rows, cg=w&3 cols (cg*32..+31).
// MODE: 1 relu -> split Ch/Cl,     3 fp32 scatter [B,H,T,DK] -> C,
//       4 split scatter (scaled) -> Ch/Cl [bh][t][16],
//       5 LN -> split,  6 LN+residual -> split,  7 LN+residual -> fp32 C
template <int MODE>
__device__ __forceinline__ void gemm_body(
        uint32_t (*Wh)[68], uint32_t (*Wl)[68],
        float (*ssum)[4], float (*ssq)[4],
        const uint32_t* __restrict__ Ah, const uint32_t* __restrict__ Al,
        const uint32_t* __restrict__ Wph, const uint32_t* __restrict__ Wpl,
        const float* __restrict__ bias,
        const uint32_t* __restrict__ Rh, const uint32_t* __restrict__ Rl,
        const float* __restrict__ lng, const float* __restrict__ lnb,
        float* __restrict__ C, uint32_t* __restrict__ Ch, uint32_t* __restrict__ Cl,
        float scl, int m0) {
    int tid = threadIdx.x;
    int w = tid >> 5, lane = tid & 31;
    int lq = lane >> 2, lr = lane & 3;
    int rg = w >> 2, cg = w & 3;

    // stage pre-split W tile: 128 n-rows x 64 kp (uint4 copies)
    #pragma unroll
    for (int i = 0; i < 8; i++) {
        int idx = tid + i * 256;            // 0..2047 uint4s
        int n = idx >> 4, u4 = (idx & 15) * 4;
        *(uint4*)&Wh[n][u4] = *(const uint4*)&Wph[(size_t)n * 64 + u4];
    }
    #pragma unroll
    for (int i = 0; i < 8; i++) {
        int idx = tid + i * 256;
        int n = idx >> 4, u4 = (idx & 15) * 4;
        *(uint4*)&Wl[n][u4] = *(const uint4*)&Wpl[(size_t)n * 64 + u4];
    }

    int mrow = m0 + rg * 16 + lq;
    const uint32_t* Ah0 = Ah + (size_t)mrow * 64;
    const uint32_t* Al0 = Al + (size_t)mrow * 64;
    float acc[4][4] = {};
    __syncthreads();

    #pragma unroll
    for (int kc = 0; kc < 8; kc++) {
        int off = kc * 8 + 2 * lr;
        uint2 h0 = *(const uint2*)&Ah0[off];
        uint2 h1 = *(const uint2*)&Ah0[512 + off];
        uint2 lo0 = *(const uint2*)&Al0[off];
        uint2 lo1 = *(const uint2*)&Al0[512 + off];
        uint32_t ah[4] = { h0.x, h1.x, h0.y, h1.y };
        uint32_t al[4] = { lo0.x, lo1.x, lo0.y, lo1.y };
        #pragma unroll
        for (int nt = 0; nt < 4; nt++) {
            int n = cg * 32 + nt * 8 + lq;
            const uint32_t* ph = &Wh[n][kc * 8 + lr];
            const uint32_t* pl = &Wl[n][kc * 8 + lr];
            uint32_t bh2[2] = { ph[0], ph[4] };
            uint32_t bl2[2] = { pl[0], pl[4] };
            mma16816(acc[nt], ah, bh2);
            mma16816(acc[nt], ah, bl2);
            mma16816(acc[nt], al, bh2);
        }
    }

    if (MODE == 5 || MODE == 6 || MODE == 7) {
        float xs[4][4];
        #pragma unroll
        for (int nt = 0; nt < 4; nt++) {
            int n = cg * 32 + nt * 8 + 2 * lr;
            float2 bv = *(const float2*)&bias[n];
            xs[nt][0] = acc[nt][0] + bv.x;
            xs[nt][1] = acc[nt][1] + bv.y;
            xs[nt][2] = acc[nt][2] + bv.x;
            xs[nt][3] = acc[nt][3] + bv.y;
            if (MODE == 6 || MODE == 7) {
                int wi = widx(cg * 16 + nt * 4 + lr);
                float2 r0 = unsplit(Rh[(size_t)mrow * 64 + wi], Rl[(size_t)mrow * 64 + wi]);
                float2 r1 = unsplit(Rh[(size_t)(mrow + 8) * 64 + wi], Rl[(size_t)(mrow + 8) * 64 + wi]);
                xs[nt][0] += r0.x; xs[nt][1] += r0.y;
                xs[nt][2] += r1.x; xs[nt][3] += r1.y;
            }
        }
        float sA = 0, qA = 0, sB = 0, qB = 0;
        #pragma unroll
        for (int nt = 0; nt < 4; nt++) {
            sA += xs[nt][0] + xs[nt][1];
            qA += xs[nt][0]*xs[nt][0] + xs[nt][1]*xs[nt][1];
            sB += xs[nt][2] + xs[nt][3];
            qB += xs[nt][2]*xs[nt][2] + xs[nt][3]*xs[nt][3];
        }
        #pragma unroll
        for (int o2 = 1; o2 < 4; o2 <<= 1) {
            sA += __shfl_xor_sync(0xffffffff, sA, o2);
            qA += __shfl_xor_sync(0xffffffff, qA, o2);
            sB += __shfl_xor_sync(0xffffffff, sB, o2);
            qB += __shfl_xor_sync(0xffffffff, qB, o2);
        }
        int ra = rg * 16 + lq, rb = ra + 8;
        if (lr == 0) {
            ssum[ra][cg] = sA; ssq[ra][cg] = qA;
            ssum[rb][cg] = sB; ssq[rb][cg] = qB;
        }
        __syncthreads();
        float fsA = ssum[ra][0] + ssum[ra][1] + ssum[ra][2] + ssum[ra][3];
        float fqA = ssq[ra][0] + ssq[ra][1] + ssq[ra][2] + ssq[ra][3];
        float fsB = ssum[rb][0] + ssum[rb][1] + ssum[rb][2] + ssum[rb][3];
        float fqB = ssq[rb][0] + ssq[rb][1] + ssq[rb][2] + ssq[rb][3];
        float muA = fsA * (1.0f / 128.0f);
        float muB = fsB * (1.0f / 128.0f);
        float rA = rsqrtf(fqA * (1.0f / 128.0f) - muA * muA + LN_EPS);
        float rB = rsqrtf(fqB * (1.0f / 128.0f) - muB * muB + LN_EPS);
        #pragma unroll
        for (int nt = 0; nt < 4; nt++) {
            int n = cg * 32 + nt * 8 + 2 * lr;
            float2 gv  = *(const float2*)&lng[n];
            float2 bv2 = *(const float2*)&lnb[n];
            float y00 = gv.x * (xs[nt][0] - muA) * rA + bv2.x;
            float y01 = gv.y * (xs[nt][1] - muA) * rA + bv2.y;
            float y10 = gv.x * (xs[nt][2] - muB) * rB + bv2.x;
            float y11 = gv.y * (xs[nt][3] - muB) * rB + bv2.y;
            if (MODE == 7) {
                *(float2*)&C[(size_t)mrow * 128 + n] = make_float2(y00, y01);
                *(float2*)&C[(size_t)(mrow + 8) * 128 + n] = make_float2(y10, y11);
            } else {
                int wi = widx(cg * 16 + nt * 4 + lr);
                uint32_t hi, lo;
                split2(y00, y01, hi, lo);
                Ch[(size_t)mrow * 64 + wi] = hi; Cl[(size_t)mrow * 64 + wi] = lo;
                split2(y10, y11, hi, lo);
                Ch[(size_t)(mrow + 8) * 64 + wi] = hi; Cl[(size_t)(mrow + 8) * 64 + wi] = lo;
            }
        }
        return;
    }

    #pragma unroll
    for (int nt = 0; nt < 4; nt++) {
        int n = cg * 32 + nt * 8 + 2 * lr;
        float2 bv = *(const float2*)&bias[n];
        float2 o0 = { acc[nt][0] + bv.x, acc[nt][1] + bv.y };
        float2 o1 = { acc[nt][2] + bv.x, acc[nt][3] + bv.y };
        if (MODE == 1) {
            o0.x = fmaxf(o0.x, 0.f); o0.y = fmaxf(o0.y, 0.f);
            o1.x = fmaxf(o1.x, 0.f); o1.y = fmaxf(o1.y, 0.f);
            int wi = widx(cg * 16 + nt * 4 + lr);
            uint32_t hi, lo;
            split2(o0.x, o0.y, hi, lo);
            Ch[(size_t)mrow * 64 + wi] = hi; Cl[(size_t)mrow * 64 + wi] = lo;
            split2(o1.x, o1.y, hi, lo);
            Ch[(size_t)(mrow + 8) * 64 + wi] = hi; Cl[(size_t)(mrow + 8) * 64 + wi] = lo;
        }
        if (MODE == 3) {
            int dk = nt * 8 + 2 * lr;
            int b0i = mrow >> 11, t0i = mrow & 2047;
            *(float2*)&C[(((b0i << 2) + cg) * 2048 + t0i) * 32 + dk] = o0;
            int b1i = (mrow + 8) >> 11, t1i = (mrow + 8) & 2047;
            *(float2*)&C[(((b1i << 2) + cg) * 2048 + t1i) * 32 + dk] = o1;
        }
        if (MODE == 4) {
            int dp = nt * 4 + lr;
            int b0i = mrow >> 11, t0i = mrow & 2047;
            uint32_t hi, lo;
            split2(o0.x * scl, o0.y * scl, hi, lo);
            size_t idx0 = ((size_t)((b0i << 2) + cg) * 2048 + t0i) * 16 + dp;
            Ch[idx0] = hi; Cl[idx0] = lo;
            int b1i = (mrow + 8) >> 11, t1i = (mrow + 8) & 2047;
            split2(o1.x * scl, o1.y * scl, hi, lo);
            size_t idx1 = ((size_t)((b1i << 2) + cg) * 2048 + t1i) * 16 + dp;
            Ch[idx1] = hi; Cl[idx1] = lo;
        }
    }
}

template <int MODE>
__global__ __launch_bounds__(256) void gemm_mma_kernel(
        const uint32_t* __restrict__ Ah, const uint32_t* __restrict__ Al,
        const uint32_t* __restrict__ Wph, const uint32_t* __restrict__ Wpl,
        const float* __restrict__ bias,
        const uint32_t* __restrict__ Rh, const uint32_t* __restrict__ Rl,
        const float* __restrict__ lng, const float* __restrict__ lnb,
        float* __restrict__ C, uint32_t* __restrict__ Ch, uint32_t* __restrict__ Cl) {
    extern __shared__ uint32_t dyn[];
    uint32_t (*Wh)[68] = (uint32_t(*)[68])dyn;
    uint32_t (*Wl)[68] = (uint32_t(*)[68])(dyn + 128 * 68);
    float (*ssum)[4] = (float(*)[4])(dyn + 2 * 128 * 68);
    float (*ssq)[4]  = (float(*)[4])(dyn + 2 * 128 * 68 + 128);
    gemm_body<MODE>(Wh, Wl, ssum, ssq, Ah, Al, Wph, Wpl, bias, Rh, Rl, lng, lnb,
                    C, Ch, Cl, 1.0f, blockIdx.x * 32);
}

// fused Q/K/V: grid (256, 3).
__global__ __launch_bounds__(256) void qkv_mma_kernel(
        const uint32_t* __restrict__ Ah, const uint32_t* __restrict__ Al,
        const uint32_t* __restrict__ Wqh, const uint32_t* __restrict__ Wql, const float* __restrict__ bq,
        const uint32_t* __restrict__ Wkh, const uint32_t* __restrict__ Wkl, const float* __restrict__ bk,
        const uint32_t* __restrict__ Wvh, const uint32_t* __restrict__ Wvl, const float* __restrict__ bv,
        uint32_t* __restrict__ qh, uint32_t* __restrict__ ql,
        uint32_t* __restrict__ kh, uint32_t* __restrict__ kl,
        float* __restrict__ v) {
    extern __shared__ uint32_t dyn[];
    uint32_t (*Wh)[68] = (uint32_t(*)[68])dyn;
    uint32_t (*Wl)[68] = (uint32_t(*)[68])(dyn + 128 * 68);
    float (*ssum)[4] = (float(*)[4])(dyn + 2 * 128 * 68);
    float (*ssq)[4]  = (float(*)[4])(dyn + 2 * 128 * 68 + 128);
    int m0 = blockIdx.x * 32;
    int sel = blockIdx.y;
    const float QSCL = 0.17677669529663687f * 1.4426950408889634f;  // 1/sqrt(32)*log2(e)
    if (sel == 0) {
        gemm_body<4>(Wh, Wl, ssum, ssq, Ah, Al, Wqh, Wql, bq, nullptr, nullptr,
                     nullptr, nullptr, nullptr, qh, ql, QSCL, m0);
    } else if (sel == 1) {
        gemm_body<4>(Wh, Wl, ssum, ssq, Ah, Al, Wkh, Wkl, bk, nullptr, nullptr,
                     nullptr, nullptr, nullptr, kh, kl, 1.0f, m0);
    } else {
        gemm_body<3>(Wh, Wl, ssum, ssq, Ah, Al, Wvh, Wvl, bv, nullptr, nullptr,
                     nullptr, nullptr, v, nullptr, nullptr, 1.0f, m0);
    }
}

// -------------------- flash attention (pre-split, split-ctx output) --------------
__global__ __launch_bounds__(256) void attn_kernel(
        const uint32_t* __restrict__ Qh, const uint32_t* __restrict__ Ql,
        const uint32_t* __restrict__ Kh, const uint32_t* __restrict__ Kl,
        const uint32_t* __restrict__ Vh, const uint32_t* __restrict__ Vl,
        uint32_t* __restrict__ Ch, uint32_t* __restrict__ Cl) {
    __shared__ __align__(16) uint32_t Ksh[2][64 * 20];
    __shared__ __align__(16) uint32_t Ksl[2][64 * 20];
    __shared__ __align__(16) uint32_t Vsh[2][32 * 36];
    __shared__ __align__(16) uint32_t Vsl[2][32 * 36];

    int bid = blockIdx.x;
    int bh  = bid >> 4;
    int qc  = bid & 15;
    int q0  = qc * 128;
    int tid = threadIdx.x;
    int w    = tid >> 5;
    int lane = tid & 31;
    int lq   = lane >> 2;
    int lr   = lane & 3;
    int row0 = q0 + w * 16 + lq;

    const uint32_t* QhB = Qh + (size_t)bh * 2048 * 16;
    const uint32_t* QlB = Ql + (size_t)bh * 2048 * 16;
    const uint32_t* KhB = Kh + (size_t)bh * 2048 * 16;
    const uint32_t* KlB = Kl + (size_t)bh * 2048 * 16;
    const uint32_t* VhB = Vh + (size_t)bh * 32 * 1024;
    const uint32_t* VlB = Vl + (size_t)bh * 32 * 1024;

    uint32_t qh[2][4], ql[2][4];
    #pragma unroll
    for (int c2 = 0; c2 < 2; c2++) {
        #pragma unroll
        for (int r = 0; r < 4; r++) {
            int row = row0 + ((r & 1) ? 8 : 0);
            int dp = c2 * 8 + lr + ((r >= 2) ? 4 : 0);
            qh[c2][r] = QhB[(size_t)row * 16 + dp];
            ql[c2][r] = QlB[(size_t)row * 16 + dp];
        }
    }

    float m0 = -1e30f, m1 = -1e30f, l0 = 0.f, l1 = 0.f;
    float o[4][4] = {};

    int kkey = tid >> 2, kdq = (tid & 3) * 4;
    int vd = tid >> 3, vkp = (tid & 7) * 4;
    uint4 kh4, kl4, vh4, vl4;
    kh4 = *(const uint4*)&KhB[kkey * 16 + kdq];
    kl4 = *(const uint4*)&KlB[kkey * 16 + kdq];
    vh4 = *(const uint4*)&VhB[vd * 1024 + vkp];
    vl4 = *(const uint4*)&VlB[vd * 1024 + vkp];

    for (int tile = 0; tile < 32; tile++) {
        int cur = tile & 1;
        *(uint4*)&Ksh[cur][kkey * 20 + kdq] = kh4;
        *(uint4*)&Ksl[cur][kkey * 20 + kdq] = kl4;
        *(uint4*)&Vsh[cur][vd * 36 + vkp] = vh4;
        *(uint4*)&Vsl[cur][vd * 36 + vkp] = vl4;

        if (tile < 31) {
            int t0 = (tile + 1) * 64, kp0 = (tile + 1) * 32;
            kh4 = *(const uint4*)&KhB[(size_t)(t0 + kkey) * 16 + kdq];
            kl4 = *(const uint4*)&KlB[(size_t)(t0 + kkey) * 16 + kdq];
            vh4 = *(const uint4*)&VhB[vd * 1024 + kp0 + vkp];
            vl4 = *(const uint4*)&VlB[vd * 1024 + kp0 + vkp];
        }
        __syncthreads();

        // ---- QK^T (log2 domain; Q pre-scaled) ----
        float c[8][4] = {};
        #pragma unroll
        for (int nt = 0; nt < 8; nt++) {
            int key = nt * 8 + lq;
            const uint32_t* kh = &Ksh[cur][key * 20 + lr];
            const uint32_t* kl = &Ksl[cur][key * 20 + lr];
            #pragma unroll
            for (int kc = 0; kc < 2; kc++) {
                uint32_t bhf[2] = { kh[8 * kc], kh[8 * kc + 4] };
                uint32_t blf[2] = { kl[8 * kc], kl[8 * kc + 4] };
                mma16816(c[nt], qh[kc], bhf);
                mma16816(c[nt], qh[kc], blf);
                mma16816(c[nt], ql[kc], bhf);
            }
        }

        // ---- online softmax (base 2) ----
        float mx0 = -1e30f, mx1 = -1e30f;
        #pragma unroll
        for (int nt = 0; nt < 8; nt++) {
            mx0 = fmaxf(mx0, fmaxf(c[nt][0], c[nt][1]));
            mx1 = fmaxf(mx1, fmaxf(c[nt][2], c[nt][3]));
        }
        mx0 = fmaxf(mx0, __shfl_xor_sync(0xffffffff, mx0, 1));
        mx0 = fmaxf(mx0, __shfl_xor_sync(0xffffffff, mx0, 2));
        mx1 = fmaxf(mx1, __shfl_xor_sync(0xffffffff, mx1, 1));
        mx1 = fmaxf(mx1, __shfl_xor_sync(0xffffffff, mx1, 2));
        float nm0 = fmaxf(m0, mx0), nm1 = fmaxf(m1, mx1);
        float f0 = exp2f(m0 - nm0), f1 = exp2f(m1 - nm1);
        m0 = nm0; m1 = nm1;
        l0 *= f0; l1 *= f1;
        #pragma unroll
        for (int dt = 0; dt < 4; dt++) {
            o[dt][0] *= f0; o[dt][1] *= f0;
            o[dt][2] *= f1; o[dt][3] *= f1;
        }
        #pragma unroll
        for (int nt = 0; nt < 8; nt++) {
            c[nt][0] = exp2f(c[nt][0] - m0);
            c[nt][1] = exp2f(c[nt][1] - m0);
            c[nt][2] = exp2f(c[nt][2] - m1);
            c[nt][3] = exp2f(c[nt][3] - m1);
            l0 += c[nt][0] + c[nt][1];
            l1 += c[nt][2] + c[nt][3];
        }

        // ---- P @ V ----
        #pragma unroll
        for (int kc = 0; kc < 4; kc++) {
            uint32_t ah[4], al[4];
            split2(c[2*kc][0],   c[2*kc][1],   ah[0], al[0]);
            split2(c[2*kc][2],   c[2*kc][3],   ah[1], al[1]);
            split2(c[2*kc+1][0], c[2*kc+1][1], ah[2], al[2]);
            split2(c[2*kc+1][2], c[2*kc+1][3], ah[3], al[3]);
            #pragma unroll
            for (int dt = 0; dt < 4; dt++) {
                int d = dt * 8 + lq;
                const uint32_t* vh = &Vsh[cur][d * 36 + kc * 8 + lr];
                const uint32_t* vl = &Vsl[cur][d * 36 + kc * 8 + lr];
                uint32_t bhf[2] = { vh[0], vh[4] };
                uint32_t blf[2] = { vl[0], vl[4] };
                mma16816(o[dt], ah, bhf);
                mma16816(o[dt], ah, blf);
                mma16816(o[dt], al, bhf);
            }
        }
    }

    // ---- epilogue: split ctx (widx layout) ----
    l0 += __shfl_xor_sync(0xffffffff, l0, 1);
    l0 += __shfl_xor_sync(0xffffffff, l0, 2);
    l1 += __shfl_xor_sync(0xffffffff, l1, 1);
    l1 += __shfl_xor_sync(0xffffffff, l1, 2);
    float inv0 = 1.0f / l0, inv1 = 1.0f / l1;
    int b = bh >> 2, hh = bh & 3;
    size_t r0 = (size_t)(b * TT + row0) * 64;
    size_t r1 = (size_t)(b * TT + row0 + 8) * 64;
    #pragma unroll
    for (int dt = 0; dt < 4; dt++) {
        int wi = widx(hh * 16 + dt * 4 + lr);
        uint32_t hi, lo;
        split2(o[dt][0] * inv0, o[dt][1] * inv0, hi, lo);
        Ch[r0 + wi] = hi; Cl[r0 + wi] = lo;
        split2(o[dt][2] * inv1, o[dt][3] * inv1, hi, lo);
        Ch[r1 + wi] = hi; Cl[r1 + wi] = lo;
    }
}

// -------------------- launch ------------------------------------------------------
extern "C" void kernel_launch(void* const* d_in, const int* in_sizes, int n_in,
                              void* d_out, int out_size) {
    const float* in  = (const float*)d_in[0];
    const float* Wq  = (const float*)d_in[1];
    const float* bq  = (const float*)d_in[2];
    const float* Wk  = (const float*)d_in[3];
    const float* bk  = (const float*)d_in[4];
    const float* Wv  = (const float*)d_in[5];
    const float* bv  = (const float*)d_in[6];
    const float* Wo  = (const float*)d_in[7];
    const float* bo  = (const float*)d_in[8];
    const float* W1  = (const float*)d_in[9];
    const float* b1  = (const float*)d_in[10];
    const float* W2  = (const float*)d_in[11];
    const float* b2  = (const float*)d_in[12];
    const float* lng = (const float*)d_in[13];
    const float* lnb = (const float*)d_in[14];
    float* out = (float*)d_out;

    float *v, *pe;
    uint32_t *hnh, *hnl, *tmph, *tmpl, *ctxh, *ctxl;
    uint32_t *qh, *ql, *kh, *kl, *vh, *vl, *wh, *wl;
    cudaGetSymbolAddress((void**)&v,    g_v);
    cudaGetSymbolAddress((void**)&pe,   g_pe);
    cudaGetSymbolAddress((void**)&hnh,  g_hnh);
    cudaGetSymbolAddress((void**)&hnl,  g_hnl);
    cudaGetSymbolAddress((void**)&tmph, g_tmph);
    cudaGetSymbolAddress((void**)&tmpl, g_tmpl);
    cudaGetSymbolAddress((void**)&ctxh, g_ctxh);
    cudaGetSymbolAddress((void**)&ctxl, g_ctxl);
    cudaGetSymbolAddress((void**)&qh,   g_qh);
    cudaGetSymbolAddress((void**)&ql,   g_ql);
    cudaGetSymbolAddress((void**)&kh,   g_kh);
    cudaGetSymbolAddress((void**)&kl,   g_kl);
    cudaGetSymbolAddress((void**)&vh,   g_vh);
    cudaGetSymbolAddress((void**)&vl,   g_vl);
    cudaGetSymbolAddress((void**)&wh,   g_wh);
    cudaGetSymbolAddress((void**)&wl,   g_wl);

    cudaFuncSetAttribute(gemm_mma_kernel<1>, cudaFuncAttributeMaxDynamicSharedMemorySize, SMEM_GEMM);
    cudaFuncSetAttribute(gemm_mma_kernel<5>, cudaFuncAttributeMaxDynamicSharedMemorySize, SMEM_GEMM);
    cudaFuncSetAttribute(gemm_mma_kernel<6>, cudaFuncAttributeMaxDynamicSharedMemorySize, SMEM_GEMM);
    cudaFuncSetAttribute(gemm_mma_kernel<7>, cudaFuncAttributeMaxDynamicSharedMemorySize, SMEM_GEMM);
    cudaFuncSetAttribute(qkv_mma_kernel, cudaFuncAttributeMaxDynamicSharedMemorySize, SMEM_GEMM);

    pe_kernel<<<128, 256>>>(pe);
    wsplit_kernel<<<dim3(64, 6), 256>>>(Wq, Wk, Wv, Wo, W1, W2, wh, wl);
    addpos_ln_kernel<<<ROWS / 8, 256>>>(in, pe, lng, lnb, hnh, hnl);

    for (int i = 0; i < NB; i++) {
        const uint32_t* Wqh = wh + (0 * NB + i) * 8192; const uint32_t* Wql = wl + (0 * NB + i) * 8192;
        const uint32_t* Wkh = wh + (1 * NB + i) * 8192; const uint32_t* Wkl = wl + (1 * NB + i) * 8192;
        const uint32_t* Wvh = wh + (2 * NB + i) * 8192; const uint32_t* Wvl = wl + (2 * NB + i) * 8192;
        const uint32_t* Woh = wh + (3 * NB + i) * 8192; const uint32_t* Wol = wl + (3 * NB + i) * 8192;
        const uint32_t* W1h = wh + (4 * NB + i) * 8192; const uint32_t* W1l = wl + (4 * NB + i) * 8192;
        const uint32_t* W2h = wh + (5 * NB + i) * 8192; const uint32_t* W2l = wl + (5 * NB + i) * 8192;
        const float* bqi = bq + i * DD;
        const float* bki = bk + i * DD;
        const float* bvi = bv + i * DD;
        const float* boi = bo + i * DD;
        const float* b1i = b1 + i * DD;
        const float* b2i = b2 + i * DD;

        qkv_mma_kernel<<<dim3(256, 3), 256, SMEM_GEMM>>>(hnh, hnl, Wqh, Wql, bqi,
                                                         Wkh, Wkl, bki, Wvh, Wvl, bvi,
                                                         qh, ql, kh, kl, v);
        vprep_kernel<<<512, 256>>>(v, vh, vl);
        attn_kernel<<<256, 256>>>(qh, ql, kh, kl, vh, vl, ctxh, ctxl);
        // Wo GEMM fused with pre-FFN LayerNorm -> split hn
        gemm_mma_kernel<5><<<256, 256, SMEM_GEMM>>>(ctxh, ctxl, Woh, Wol, boi,
                                                    nullptr, nullptr,
                                                    lng + (2 * i + 1) * DD, lnb + (2 * i + 1) * DD,
                                                    nullptr, hnh, hnl);
        // FFN inner (relu) -> split tmp
        gemm_mma_kernel<1><<<256, 256, SMEM_GEMM>>>(hnh, hnl, W1h, W1l, b1i,
                                                    nullptr, nullptr, nullptr, nullptr,
                                                    nullptr, tmph, tmpl);
        // FFN outer + residual + next LN -> split hn, or final LN -> fp32 out
        if (i == NB - 1) {
            gemm_mma_kernel<7><<<256, 256, SMEM_GEMM>>>(tmph, tmpl, W2h, W2l, b2i,
                                                        hnh, hnl,
                                                        lng + 3 * DD, lnb + 3 * DD,
                                                        out, nullptr, nullptr);
        } else {
            gemm_mma_kernel<6><<<256, 256, SMEM_GEMM>>>(tmph, tmpl, W2h, W2l, b2i,
                                                        hnh, hnl,
                                                        lng + (2 * i + 2) * DD, lnb + (2 * i + 2) * DD,
                                                        nullptr, hnh, hnl);
        }
    }
}

// round 10
// speedup vs baseline: 1.0470x; 1.0419x over previous
#include <cuda_runtime.h>
#include <cuda_bf16.h>
#include <stdint.h>
#include <math.h>

#define NB 2
#define BB 4
#define TT 2048
#define DD 128
#define HH 4
#define DK 32
#define ROWS (BB*TT)          // 8192
#define LN_EPS 1e-3f
#define SMEM_G128 (2*128*68*4 + 256*4)   // 70656 B (LN-fused modes)
#define SMEM_G64  (2*64*68*4)            // 34816 B (non-LN modes)

// -------------------- scratch (device globals; no allocs allowed) ------------
__device__ float g_v  [ROWS*DD];
__device__ float g_pe [TT*DD];
// split activations, fragment-major widx layout: [row][64]
__device__ uint32_t g_hnh [ROWS*64], g_hnl [ROWS*64];
__device__ uint32_t g_tmph[ROWS*64], g_tmpl[ROWS*64];
__device__ uint32_t g_ctxh[ROWS*64], g_ctxl[ROWS*64];
// split Q/K: [bh=16][t=2048][dp=16] linear dp
__device__ uint32_t g_qh[ROWS*64], g_ql[ROWS*64];
__device__ uint32_t g_kh[ROWS*64], g_kl[ROWS*64];
__device__ uint32_t g_vh[16*32*1024], g_vl[16*32*1024];
__device__ uint32_t g_wh[6*NB*8192], g_wl[6*NB*8192];

// -------------------- split-bf16 helpers ---------------------------------------
__device__ __forceinline__ uint32_t pk_bf2(float a, float b) {
    __nv_bfloat162 t = __floats2bfloat162_rn(a, b);
    return *reinterpret_cast<uint32_t*>(&t);
}
__device__ __forceinline__ void split2(float a, float b, uint32_t& h, uint32_t& l) {
    float ah = __bfloat162float(__float2bfloat16(a));
    float bh = __bfloat162float(__float2bfloat16(b));
    h = pk_bf2(ah, bh);
    l = pk_bf2(a - ah, b - bh);
}
__device__ __forceinline__ float2 unsplit(uint32_t h, uint32_t l) {
    __nv_bfloat162 hb = *reinterpret_cast<__nv_bfloat162*>(&h);
    __nv_bfloat162 lb = *reinterpret_cast<__nv_bfloat162*>(&l);
    return make_float2(__bfloat162float(hb.x) + __bfloat162float(lb.x),
                       __bfloat162float(hb.y) + __bfloat162float(lb.y));
}
// fragment-major permutation: pairs (dp, dp+4 within the 8-dp kc group) adjacent
__device__ __forceinline__ int widx(int dp) {
    return (dp & ~7) + 2 * (dp & 3) + ((dp >> 2) & 1);
}
__device__ __forceinline__ void mma16816(float c[4], const uint32_t a[4], const uint32_t b[2]) {
    asm volatile(
        "mma.sync.aligned.m16n8k16.row.col.f32.bf16.bf16.f32 "
        "{%0,%1,%2,%3}, {%4,%5,%6,%7}, {%8,%9}, {%0,%1,%2,%3};\n"
        : "+f"(c[0]), "+f"(c[1]), "+f"(c[2]), "+f"(c[3])
        : "r"(a[0]), "r"(a[1]), "r"(a[2]), "r"(a[3]), "r"(b[0]), "r"(b[1]));
}

// -------------------- positional encoding -------------------------------------
__global__ void pe_kernel(float* __restrict__ pe) {
    int i = blockIdx.x;
    double f = exp(-((double)(2 * i) / 128.0) * 9.210340371976184);
    const double TWO_PI = 6.283185307179586;
    const double INV_TWO_PI = 0.15915494309189535;
    for (int t = threadIdx.x; t < TT; t += blockDim.x) {
        double ang = (double)t * f;
        double r = ang - TWO_PI * floor(ang * INV_TWO_PI);
        float rf = (float)r;
        pe[t * DD + i] = (i & 1) ? cosf(rf) : sinf(rf);
    }
}

// -------------------- fused addpos + first LayerNorm -> split hn -----------------
__global__ void addpos_ln_kernel(const float* __restrict__ in, const float* __restrict__ pe,
                                 const float* __restrict__ g, const float* __restrict__ b,
                                 uint32_t* __restrict__ Ch, uint32_t* __restrict__ Cl) {
    int row  = blockIdx.x * 8 + (threadIdx.x >> 5);
    int lane = threadIdx.x & 31;
    int t = row & (TT - 1);
    float4 xv = ((const float4*)in)[row * 32 + lane];
    float4 pv = ((const float4*)pe)[t * 32 + lane];
    xv.x += pv.x; xv.y += pv.y; xv.z += pv.z; xv.w += pv.w;
    float s = xv.x + xv.y + xv.z + xv.w;
    #pragma unroll
    for (int o = 16; o > 0; o >>= 1) s += __shfl_xor_sync(0xffffffff, s, o);
    float mu = s * (1.0f / 128.0f);
    float dx0 = xv.x - mu, dx1 = xv.y - mu, dx2 = xv.z - mu, dx3 = xv.w - mu;
    float sq = dx0*dx0 + dx1*dx1 + dx2*dx2 + dx3*dx3;
    #pragma unroll
    for (int o = 16; o > 0; o >>= 1) sq += __shfl_xor_sync(0xffffffff, sq, o);
    float var = sq * (1.0f / 128.0f);
    float r = rsqrtf(var + LN_EPS);
    float4 gv = ((const float4*)g)[lane];
    float4 bv = ((const float4*)b)[lane];
    float y0 = gv.x * dx0 * r + bv.x;
    float y1 = gv.y * dx1 * r + bv.y;
    float y2 = gv.z * dx2 * r + bv.z;
    float y3 = gv.w * dx3 * r + bv.w;
    uint32_t h0, l0, h1, l1;
    split2(y0, y1, h0, l0);
    split2(y2, y3, h1, l1);
    int base = row * 64;
    Ch[base + widx(2 * lane)]     = h0; Cl[base + widx(2 * lane)]     = l0;
    Ch[base + widx(2 * lane + 1)] = h1; Cl[base + widx(2 * lane + 1)] = l1;
}

// -------------------- weight pre-split ------------------------------------------
__global__ void wsplit_kernel(const float* __restrict__ Wq, const float* __restrict__ Wk,
                              const float* __restrict__ Wv, const float* __restrict__ Wo,
                              const float* __restrict__ W1, const float* __restrict__ W2,
                              uint32_t* __restrict__ wh, uint32_t* __restrict__ wl) {
    const float* Ws[6] = {Wq, Wk, Wv, Wo, W1, W2};
    int fam = blockIdx.y;
    const float* W = Ws[fam];
    int idx = blockIdx.x * 256 + threadIdx.x;   // 0..16383 = NB*8192
    int layer = idx >> 13;
    int rem = idx & 8191;
    int kp = rem >> 7, n = rem & 127;
    const float* Wm = W + layer * 128 * 128;
    float w0 = Wm[(2 * kp) * 128 + n];
    float w1 = Wm[(2 * kp + 1) * 128 + n];
    uint32_t hi, lo;
    split2(w0, w1, hi, lo);
    int out = (fam * NB + layer) * 8192 + n * 64 + kp;
    wh[out] = hi;
    wl[out] = lo;
}

// -------------------- V transpose/split (smem-transposed, coalesced) -------------
// v fp32 [bh][t][32] -> Vh/Vl [bh][d 0..31][kp 0..1023]
__global__ void vprep_kernel(const float* __restrict__ v,
                             uint32_t* __restrict__ vh, uint32_t* __restrict__ vl) {
    __shared__ uint32_t sh[32][33];
    __shared__ uint32_t sl[32][33];
    int bh = blockIdx.x >> 5;
    int kp0 = (blockIdx.x & 31) * 32;
    const float* vb = v + (size_t)bh * 2048 * 32;
    uint32_t* th = vh + (size_t)bh * 32 * 1024;
    uint32_t* tl = vl + (size_t)bh * 32 * 1024;
    // read coalesced: idx = kpl*32 + d
    #pragma unroll
    for (int i = 0; i < 4; i++) {
        int idx = threadIdx.x + i * 256;   // 0..1023
        int kpl = idx >> 5;
        int d = idx & 31;
        float v0 = vb[(size_t)(2 * (kp0 + kpl)) * 32 + d];
        float v1 = vb[(size_t)(2 * (kp0 + kpl) + 1) * 32 + d];
        uint32_t hi, lo;
        split2(v0, v1, hi, lo);
        sh[d][kpl] = hi;
        sl[d][kpl] = lo;
    }
    __syncthreads();
    // write coalesced: idx = d*32 + kpl
    #pragma unroll
    for (int i = 0; i < 4; i++) {
        int idx = threadIdx.x + i * 256;
        int d = idx >> 5;
        int kpl = idx & 31;
        th[d * 1024 + kp0 + kpl] = sh[d][kpl];
        tl[d * 1024 + kp0 + kpl] = sl[d][kpl];
    }
}

// ==================== GEMM body, N=64 tile (modes 1/3/4, no LN) ====================
// block: M=64 x N=64, 8 warps: rg=w>>1 (rows m0+rg*16..), cg=w&1 (cols n0+cg*32..)
template <int MODE>
__global__ __launch_bounds__(256) void gemm64_kernel(
        const uint32_t* __restrict__ Ah, const uint32_t* __restrict__ Al,
        const uint32_t* __restrict__ Wph, const uint32_t* __restrict__ Wpl,
        const float* __restrict__ bias,
        float* __restrict__ C, uint32_t* __restrict__ Ch, uint32_t* __restrict__ Cl,
        float scl) {
    __shared__ __align__(16) uint32_t Wh[64][68];
    __shared__ __align__(16) uint32_t Wl[64][68];
    int tid = threadIdx.x;
    int w = tid >> 5, lane = tid & 31;
    int lq = lane >> 2, lr = lane & 3;
    int rg = w >> 1, cg = w & 1;
    int m0 = (blockIdx.x >> 1) * 64;
    int n0 = (blockIdx.x & 1) * 64;

    #pragma unroll
    for (int i = 0; i < 4; i++) {
        int idx = tid + i * 256;            // 0..1023 uint4s
        int n = idx >> 4, u4 = (idx & 15) * 4;
        *(uint4*)&Wh[n][u4] = *(const uint4*)&Wph[(size_t)(n0 + n) * 64 + u4];
    }
    #pragma unroll
    for (int i = 0; i < 4; i++) {
        int idx = tid + i * 256;
        int n = idx >> 4, u4 = (idx & 15) * 4;
        *(uint4*)&Wl[n][u4] = *(const uint4*)&Wpl[(size_t)(n0 + n) * 64 + u4];
    }

    int mrow = m0 + rg * 16 + lq;
    const uint32_t* Ah0 = Ah + (size_t)mrow * 64;
    const uint32_t* Al0 = Al + (size_t)mrow * 64;
    float acc[4][4] = {};
    __syncthreads();

    #pragma unroll
    for (int kc = 0; kc < 8; kc++) {
        int off = kc * 8 + 2 * lr;
        uint2 h0 = *(const uint2*)&Ah0[off];
        uint2 h1 = *(const uint2*)&Ah0[512 + off];
        uint2 lo0 = *(const uint2*)&Al0[off];
        uint2 lo1 = *(const uint2*)&Al0[512 + off];
        uint32_t ah[4] = { h0.x, h1.x, h0.y, h1.y };
        uint32_t al[4] = { lo0.x, lo1.x, lo0.y, lo1.y };
        #pragma unroll
        for (int nt = 0; nt < 4; nt++) {
            int n = cg * 32 + nt * 8 + lq;
            const uint32_t* ph = &Wh[n][kc * 8 + lr];
            const uint32_t* pl = &Wl[n][kc * 8 + lr];
            uint32_t bh2[2] = { ph[0], ph[4] };
            uint32_t bl2[2] = { pl[0], pl[4] };
            mma16816(acc[nt], ah, bh2);
            mma16816(acc[nt], ah, bl2);
            mma16816(acc[nt], al, bh2);
        }
    }

    #pragma unroll
    for (int nt = 0; nt < 4; nt++) {
        int n = n0 + cg * 32 + nt * 8 + 2 * lr;    // global col
        float2 bv = *(const float2*)&bias[n];
        float2 o0 = { acc[nt][0] + bv.x, acc[nt][1] + bv.y };
        float2 o1 = { acc[nt][2] + bv.x, acc[nt][3] + bv.y };
        if (MODE == 1) {
            o0.x = fmaxf(o0.x, 0.f); o0.y = fmaxf(o0.y, 0.f);
            o1.x = fmaxf(o1.x, 0.f); o1.y = fmaxf(o1.y, 0.f);
            int wi = widx(n >> 1);
            uint32_t hi, lo;
            split2(o0.x, o0.y, hi, lo);
            Ch[(size_t)mrow * 64 + wi] = hi; Cl[(size_t)mrow * 64 + wi] = lo;
            split2(o1.x, o1.y, hi, lo);
            Ch[(size_t)(mrow + 8) * 64 + wi] = hi; Cl[(size_t)(mrow + 8) * 64 + wi] = lo;
        }
        if (MODE == 3) {
            int hh = n >> 5, dk = n & 31;
            int b0i = mrow >> 11, t0i = mrow & 2047;
            *(float2*)&C[(((b0i << 2) + hh) * 2048 + t0i) * 32 + dk] = o0;
            int b1i = (mrow + 8) >> 11, t1i = (mrow + 8) & 2047;
            *(float2*)&C[(((b1i << 2) + hh) * 2048 + t1i) * 32 + dk] = o1;
        }
        if (MODE == 4) {
            int hh = n >> 5, dp = (n & 31) >> 1;
            int b0i = mrow >> 11, t0i = mrow & 2047;
            uint32_t hi, lo;
            split2(o0.x * scl, o0.y * scl, hi, lo);
            size_t idx0 = ((size_t)((b0i << 2) + hh) * 2048 + t0i) * 16 + dp;
            Ch[idx0] = hi; Cl[idx0] = lo;
            int b1i = (mrow + 8) >> 11, t1i = (mrow + 8) & 2047;
            split2(o1.x * scl, o1.y * scl, hi, lo);
            size_t idx1 = ((size_t)((b1i << 2) + hh) * 2048 + t1i) * 16 + dp;
            Ch[idx1] = hi; Cl[idx1] = lo;
        }
    }
}

// fused Q/K/V on the N=64 tile: grid (256, 3)
__global__ __launch_bounds__(256) void qkv64_kernel(
        const uint32_t* __restrict__ Ah, const uint32_t* __restrict__ Al,
        const uint32_t* __restrict__ Wqh, const uint32_t* __restrict__ Wql, const float* __restrict__ bq,
        const uint32_t* __restrict__ Wkh, const uint32_t* __restrict__ Wkl, const float* __restrict__ bk,
        const uint32_t* __restrict__ Wvh, const uint32_t* __restrict__ Wvl, const float* __restrict__ bv,
        uint32_t* __restrict__ qh, uint32_t* __restrict__ ql,
        uint32_t* __restrict__ kh, uint32_t* __restrict__ kl,
        float* __restrict__ v) {
    __shared__ __align__(16) uint32_t Wh[64][68];
    __shared__ __align__(16) uint32_t Wl[64][68];
    int tid = threadIdx.x;
    int w = tid >> 5, lane = tid & 31;
    int lq = lane >> 2, lr = lane & 3;
    int rg = w >> 1, cg = w & 1;
    int m0 = (blockIdx.x >> 1) * 64;
    int n0 = (blockIdx.x & 1) * 64;
    int sel = blockIdx.y;
    const float QSCL = 0.17677669529663687f * 1.4426950408889634f;
    const uint32_t* Wph = (sel == 0) ? Wqh : (sel == 1) ? Wkh : Wvh;
    const uint32_t* Wpl = (sel == 0) ? Wql : (sel == 1) ? Wkl : Wvl;
    const float* bias   = (sel == 0) ? bq  : (sel == 1) ? bk  : bv;
    float scl = (sel == 0) ? QSCL : 1.0f;

    #pragma unroll
    for (int i = 0; i < 4; i++) {
        int idx = tid + i * 256;
        int n = idx >> 4, u4 = (idx & 15) * 4;
        *(uint4*)&Wh[n][u4] = *(const uint4*)&Wph[(size_t)(n0 + n) * 64 + u4];
    }
    #pragma unroll
    for (int i = 0; i < 4; i++) {
        int idx = tid + i * 256;
        int n = idx >> 4, u4 = (idx & 15) * 4;
        *(uint4*)&Wl[n][u4] = *(const uint4*)&Wpl[(size_t)(n0 + n) * 64 + u4];
    }

    int mrow = m0 + rg * 16 + lq;
    const uint32_t* Ah0 = Ah + (size_t)mrow * 64;
    const uint32_t* Al0 = Al + (size_t)mrow * 64;
    float acc[4][4] = {};
    __syncthreads();

    #pragma unroll
    for (int kc = 0; kc < 8; kc++) {
        int off = kc * 8 + 2 * lr;
        uint2 h0 = *(const uint2*)&Ah0[off];
        uint2 h1 = *(const uint2*)&Ah0[512 + off];
        uint2 lo0 = *(const uint2*)&Al0[off];
        uint2 lo1 = *(const uint2*)&Al0[512 + off];
        uint32_t ah[4] = { h0.x, h1.x, h0.y, h1.y };
        uint32_t al[4] = { lo0.x, lo1.x, lo0.y, lo1.y };
        #pragma unroll
        for (int nt = 0; nt < 4; nt++) {
            int n = cg * 32 + nt * 8 + lq;
            const uint32_t* ph = &Wh[n][kc * 8 + lr];
            const uint32_t* pl = &Wl[n][kc * 8 + lr];
            uint32_t bh2[2] = { ph[0], ph[4] };
            uint32_t bl2[2] = { pl[0], pl[4] };
            mma16816(acc[nt], ah, bh2);
            mma16816(acc[nt], ah, bl2);
            mma16816(acc[nt], al, bh2);
        }
    }

    #pragma unroll
    for (int nt = 0; nt < 4; nt++) {
        int n = n0 + cg * 32 + nt * 8 + 2 * lr;
        float2 bv2 = *(const float2*)&bias[n];
        float2 o0 = { acc[nt][0] + bv2.x, acc[nt][1] + bv2.y };
        float2 o1 = { acc[nt][2] + bv2.x, acc[nt][3] + bv2.y };
        int hh = n >> 5;
        int b0i = mrow >> 11, t0i = mrow & 2047;
        int b1i = (mrow + 8) >> 11, t1i = (mrow + 8) & 2047;
        if (sel == 2) {
            int dk = n & 31;
            *(float2*)&v[(((b0i << 2) + hh) * 2048 + t0i) * 32 + dk] = o0;
            *(float2*)&v[(((b1i << 2) + hh) * 2048 + t1i) * 32 + dk] = o1;
        } else {
            uint32_t* Ch = (sel == 0) ? qh : kh;
            uint32_t* Cl = (sel == 0) ? ql : kl;
            int dp = (n & 31) >> 1;
            uint32_t hi, lo;
            split2(o0.x * scl, o0.y * scl, hi, lo);
            size_t idx0 = ((size_t)((b0i << 2) + hh) * 2048 + t0i) * 16 + dp;
            Ch[idx0] = hi; Cl[idx0] = lo;
            split2(o1.x * scl, o1.y * scl, hi, lo);
            size_t idx1 = ((size_t)((b1i << 2) + hh) * 2048 + t1i) * 16 + dp;
            Ch[idx1] = hi; Cl[idx1] = lo;
        }
    }
}

// ==================== GEMM body, N=128 tile (LN modes 5/6/7) =====================
template <int MODE>
__global__ __launch_bounds__(256) void gemm_mma_kernel(
        const uint32_t* __restrict__ Ah, const uint32_t* __restrict__ Al,
        const uint32_t* __restrict__ Wph, const uint32_t* __restrict__ Wpl,
        const float* __restrict__ bias,
        const uint32_t* __restrict__ Rh, const uint32_t* __restrict__ Rl,
        const float* __restrict__ lng, const float* __restrict__ lnb,
        float* __restrict__ C, uint32_t* __restrict__ Ch, uint32_t* __restrict__ Cl) {
    extern __shared__ uint32_t dyn[];
    uint32_t (*Wh)[68] = (uint32_t(*)[68])dyn;
    uint32_t (*Wl)[68] = (uint32_t(*)[68])(dyn + 128 * 68);
    float (*ssum)[4] = (float(*)[4])(dyn + 2 * 128 * 68);
    float (*ssq)[4]  = (float(*)[4])(dyn + 2 * 128 * 68 + 128);
    int tid = threadIdx.x;
    int w = tid >> 5, lane = tid & 31;
    int lq = lane >> 2, lr = lane & 3;
    int rg = w >> 2, cg = w & 3;
    int m0 = blockIdx.x * 32;

    #pragma unroll
    for (int i = 0; i < 8; i++) {
        int idx = tid + i * 256;
        int n = idx >> 4, u4 = (idx & 15) * 4;
        *(uint4*)&Wh[n][u4] = *(const uint4*)&Wph[(size_t)n * 64 + u4];
    }
    #pragma unroll
    for (int i = 0; i < 8; i++) {
        int idx = tid + i * 256;
        int n = idx >> 4, u4 = (idx & 15) * 4;
        *(uint4*)&Wl[n][u4] = *(const uint4*)&Wpl[(size_t)n * 64 + u4];
    }

    int mrow = m0 + rg * 16 + lq;
    const uint32_t* Ah0 = Ah + (size_t)mrow * 64;
    const uint32_t* Al0 = Al + (size_t)mrow * 64;
    float acc[4][4] = {};
    __syncthreads();

    #pragma unroll
    for (int kc = 0; kc < 8; kc++) {
        int off = kc * 8 + 2 * lr;
        uint2 h0 = *(const uint2*)&Ah0[off];
        uint2 h1 = *(const uint2*)&Ah0[512 + off];
        uint2 lo0 = *(const uint2*)&Al0[off];
        uint2 lo1 = *(const uint2*)&Al0[512 + off];
        uint32_t ah[4] = { h0.x, h1.x, h0.y, h1.y };
        uint32_t al[4] = { lo0.x, lo1.x, lo0.y, lo1.y };
        #pragma unroll
        for (int nt = 0; nt < 4; nt++) {
            int n = cg * 32 + nt * 8 + lq;
            const uint32_t* ph = &Wh[n][kc * 8 + lr];
            const uint32_t* pl = &Wl[n][kc * 8 + lr];
            uint32_t bh2[2] = { ph[0], ph[4] };
            uint32_t bl2[2] = { pl[0], pl[4] };
            mma16816(acc[nt], ah, bh2);
            mma16816(acc[nt], ah, bl2);
            mma16816(acc[nt], al, bh2);
        }
    }

    float xs[4][4];
    #pragma unroll
    for (int nt = 0; nt < 4; nt++) {
        int n = cg * 32 + nt * 8 + 2 * lr;
        float2 bv = *(const float2*)&bias[n];
        xs[nt][0] = acc[nt][0] + bv.x;
        xs[nt][1] = acc[nt][1] + bv.y;
        xs[nt][2] = acc[nt][2] + bv.x;
        xs[nt][3] = acc[nt][3] + bv.y;
        if (MODE == 6 || MODE == 7) {
            int wi = widx(cg * 16 + nt * 4 + lr);
            float2 r0 = unsplit(Rh[(size_t)mrow * 64 + wi], Rl[(size_t)mrow * 64 + wi]);
            float2 r1 = unsplit(Rh[(size_t)(mrow + 8) * 64 + wi], Rl[(size_t)(mrow + 8) * 64 + wi]);
            xs[nt][0] += r0.x; xs[nt][1] += r0.y;
            xs[nt][2] += r1.x; xs[nt][3] += r1.y;
        }
    }
    float sA = 0, qA = 0, sB = 0, qB = 0;
    #pragma unroll
    for (int nt = 0; nt < 4; nt++) {
        sA += xs[nt][0] + xs[nt][1];
        qA += xs[nt][0]*xs[nt][0] + xs[nt][1]*xs[nt][1];
        sB += xs[nt][2] + xs[nt][3];
        qB += xs[nt][2]*xs[nt][2] + xs[nt][3]*xs[nt][3];
    }
    #pragma unroll
    for (int o2 = 1; o2 < 4; o2 <<= 1) {
        sA += __shfl_xor_sync(0xffffffff, sA, o2);
        qA += __shfl_xor_sync(0xffffffff, qA, o2);
        sB += __shfl_xor_sync(0xffffffff, sB, o2);
        qB += __shfl_xor_sync(0xffffffff, qB, o2);
    }
    int ra = rg * 16 + lq, rb = ra + 8;
    if (lr == 0) {
        ssum[ra][cg] = sA; ssq[ra][cg] = qA;
        ssum[rb][cg] = sB; ssq[rb][cg] = qB;
    }
    __syncthreads();
    float fsA = ssum[ra][0] + ssum[ra][1] + ssum[ra][2] + ssum[ra][3];
    float fqA = ssq[ra][0] + ssq[ra][1] + ssq[ra][2] + ssq[ra][3];
    float fsB = ssum[rb][0] + ssum[rb][1] + ssum[rb][2] + ssum[rb][3];
    float fqB = ssq[rb][0] + ssq[rb][1] + ssq[rb][2] + ssq[rb][3];
    float muA = fsA * (1.0f / 128.0f);
    float muB = fsB * (1.0f / 128.0f);
    float rA = rsqrtf(fqA * (1.0f / 128.0f) - muA * muA + LN_EPS);
    float rB = rsqrtf(fqB * (1.0f / 128.0f) - muB * muB + LN_EPS);
    #pragma unroll
    for (int nt = 0; nt < 4; nt++) {
        int n = cg * 32 + nt * 8 + 2 * lr;
        float2 gv  = *(const float2*)&lng[n];
        float2 bv2 = *(const float2*)&lnb[n];
        float y00 = gv.x * (xs[nt][0] - muA) * rA + bv2.x;
        float y01 = gv.y * (xs[nt][1] - muA) * rA + bv2.y;
        float y10 = gv.x * (xs[nt][2] - muB) * rB + bv2.x;
        float y11 = gv.y * (xs[nt][3] - muB) * rB + bv2.y;
        if (MODE == 7) {
            *(float2*)&C[(size_t)mrow * 128 + n] = make_float2(y00, y01);
            *(float2*)&C[(size_t)(mrow + 8) * 128 + n] = make_float2(y10, y11);
        } else {
            int wi = widx(cg * 16 + nt * 4 + lr);
            uint32_t hi, lo;
            split2(y00, y01, hi, lo);
            Ch[(size_t)mrow * 64 + wi] = hi; Cl[(size_t)mrow * 64 + wi] = lo;
            split2(y10, y11, hi, lo);
            Ch[(size_t)(mrow + 8) * 64 + wi] = hi; Cl[(size_t)(mrow + 8) * 64 + wi] = lo;
        }
    }
}

// -------------------- flash attention (pre-split, split-ctx output) --------------
__global__ __launch_bounds__(256) void attn_kernel(
        const uint32_t* __restrict__ Qh, const uint32_t* __restrict__ Ql,
        const uint32_t* __restrict__ Kh, const uint32_t* __restrict__ Kl,
        const uint32_t* __restrict__ Vh, const uint32_t* __restrict__ Vl,
        uint32_t* __restrict__ Ch, uint32_t* __restrict__ Cl) {
    __shared__ __align__(16) uint32_t Ksh[2][64 * 20];
    __shared__ __align__(16) uint32_t Ksl[2][64 * 20];
    __shared__ __align__(16) uint32_t Vsh[2][32 * 36];
    __shared__ __align__(16) uint32_t Vsl[2][32 * 36];

    int bid = blockIdx.x;
    int bh  = bid >> 4;
    int qc  = bid & 15;
    int q0  = qc * 128;
    int tid = threadIdx.x;
    int w    = tid >> 5;
    int lane = tid & 31;
    int lq   = lane >> 2;
    int lr   = lane & 3;
    int row0 = q0 + w * 16 + lq;

    const uint32_t* QhB = Qh + (size_t)bh * 2048 * 16;
    const uint32_t* QlB = Ql + (size_t)bh * 2048 * 16;
    const uint32_t* KhB = Kh + (size_t)bh * 2048 * 16;
    const uint32_t* KlB = Kl + (size_t)bh * 2048 * 16;
    const uint32_t* VhB = Vh + (size_t)bh * 32 * 1024;
    const uint32_t* VlB = Vl + (size_t)bh * 32 * 1024;

    uint32_t qh[2][4], ql[2][4];
    #pragma unroll
    for (int c2 = 0; c2 < 2; c2++) {
        #pragma unroll
        for (int r = 0; r < 4; r++) {
            int row = row0 + ((r & 1) ? 8 : 0);
            int dp = c2 * 8 + lr + ((r >= 2) ? 4 : 0);
            qh[c2][r] = QhB[(size_t)row * 16 + dp];
            ql[c2][r] = QlB[(size_t)row * 16 + dp];
        }
    }

    float m0 = -1e30f, m1 = -1e30f, l0 = 0.f, l1 = 0.f;
    float o[4][4] = {};

    int kkey = tid >> 2, kdq = (tid & 3) * 4;
    int vd = tid >> 3, vkp = (tid & 7) * 4;
    uint4 kh4, kl4, vh4, vl4;
    kh4 = *(const uint4*)&KhB[kkey * 16 + kdq];
    kl4 = *(const uint4*)&KlB[kkey * 16 + kdq];
    vh4 = *(const uint4*)&VhB[vd * 1024 + vkp];
    vl4 = *(const uint4*)&VlB[vd * 1024 + vkp];

    for (int tile = 0; tile < 32; tile++) {
        int cur = tile & 1;
        *(uint4*)&Ksh[cur][kkey * 20 + kdq] = kh4;
        *(uint4*)&Ksl[cur][kkey * 20 + kdq] = kl4;
        *(uint4*)&Vsh[cur][vd * 36 + vkp] = vh4;
        *(uint4*)&Vsl[cur][vd * 36 + vkp] = vl4;

        if (tile < 31) {
            int t0 = (tile + 1) * 64, kp0 = (tile + 1) * 32;
            kh4 = *(const uint4*)&KhB[(size_t)(t0 + kkey) * 16 + kdq];
            kl4 = *(const uint4*)&KlB[(size_t)(t0 + kkey) * 16 + kdq];
            vh4 = *(const uint4*)&VhB[vd * 1024 + kp0 + vkp];
            vl4 = *(const uint4*)&VlB[vd * 1024 + kp0 + vkp];
        }
        __syncthreads();

        // ---- QK^T (log2 domain; Q pre-scaled) ----
        float c[8][4] = {};
        #pragma unroll
        for (int nt = 0; nt < 8; nt++) {
            int key = nt * 8 + lq;
            const uint32_t* kh = &Ksh[cur][key * 20 + lr];
            const uint32_t* kl = &Ksl[cur][key * 20 + lr];
            #pragma unroll
            for (int kc = 0; kc < 2; kc++) {
                uint32_t bhf[2] = { kh[8 * kc], kh[8 * kc + 4] };
                uint32_t blf[2] = { kl[8 * kc], kl[8 * kc + 4] };
                mma16816(c[nt], qh[kc], bhf);
                mma16816(c[nt], qh[kc], blf);
                mma16816(c[nt], ql[kc], bhf);
            }
        }

        // ---- online softmax (base 2) ----
        float mx0 = -1e30f, mx1 = -1e30f;
        #pragma unroll
        for (int nt = 0; nt < 8; nt++) {
            mx0 = fmaxf(mx0, fmaxf(c[nt][0], c[nt][1]));
            mx1 = fmaxf(mx1, fmaxf(c[nt][2], c[nt][3]));
        }
        mx0 = fmaxf(mx0, __shfl_xor_sync(0xffffffff, mx0, 1));
        mx0 = fmaxf(mx0, __shfl_xor_sync(0xffffffff, mx0, 2));
        mx1 = fmaxf(mx1, __shfl_xor_sync(0xffffffff, mx1, 1));
        mx1 = fmaxf(mx1, __shfl_xor_sync(0xffffffff, mx1, 2));
        float nm0 = fmaxf(m0, mx0), nm1 = fmaxf(m1, mx1);
        float f0 = exp2f(m0 - nm0), f1 = exp2f(m1 - nm1);
        m0 = nm0; m1 = nm1;
        l0 *= f0; l1 *= f1;
        #pragma unroll
        for (int dt = 0; dt < 4; dt++) {
            o[dt][0] *= f0; o[dt][1] *= f0;
            o[dt][2] *= f1; o[dt][3] *= f1;
        }
        #pragma unroll
        for (int nt = 0; nt < 8; nt++) {
            c[nt][0] = exp2f(c[nt][0] - m0);
            c[nt][1] = exp2f(c[nt][1] - m0);
            c[nt][2] = exp2f(c[nt][2] - m1);
            c[nt][3] = exp2f(c[nt][3] - m1);
            l0 += c[nt][0] + c[nt][1];
            l1 += c[nt][2] + c[nt][3];
        }

        // ---- P @ V ----
        #pragma unroll
        for (int kc = 0; kc < 4; kc++) {
            uint32_t ah[4], al[4];
            split2(c[2*kc][0],   c[2*kc][1],   ah[0], al[0]);
            split2(c[2*kc][2],   c[2*kc][3],   ah[1], al[1]);
            split2(c[2*kc+1][0], c[2*kc+1][1], ah[2], al[2]);
            split2(c[2*kc+1][2], c[2*kc+1][3], ah[3], al[3]);
            #pragma unroll
            for (int dt = 0; dt < 4; dt++) {
                int d = dt * 8 + lq;
                const uint32_t* vh = &Vsh[cur][d * 36 + kc * 8 + lr];
                const uint32_t* vl = &Vsl[cur][d * 36 + kc * 8 + lr];
                uint32_t bhf[2] = { vh[0], vh[4] };
                uint32_t blf[2] = { vl[0], vl[4] };
                mma16816(o[dt], ah, bhf);
                mma16816(o[dt], ah, blf);
                mma16816(o[dt], al, bhf);
            }
        }
    }

    // ---- epilogue: split ctx (widx layout) ----
    l0 += __shfl_xor_sync(0xffffffff, l0, 1);
    l0 += __shfl_xor_sync(0xffffffff, l0, 2);
    l1 += __shfl_xor_sync(0xffffffff, l1, 1);
    l1 += __shfl_xor_sync(0xffffffff, l1, 2);
    float inv0 = 1.0f / l0, inv1 = 1.0f / l1;
    int b = bh >> 2, hh = bh & 3;
    size_t r0 = (size_t)(b * TT + row0) * 64;
    size_t r1 = (size_t)(b * TT + row0 + 8) * 64;
    #pragma unroll
    for (int dt = 0; dt < 4; dt++) {
        int wi = widx(hh * 16 + dt * 4 + lr);
        uint32_t hi, lo;
        split2(o[dt][0] * inv0, o[dt][1] * inv0, hi, lo);
        Ch[r0 + wi] = hi; Cl[r0 + wi] = lo;
        split2(o[dt][2] * inv1, o[dt][3] * inv1, hi, lo);
        Ch[r1 + wi] = hi; Cl[r1 + wi] = lo;
    }
}

// -------------------- launch ------------------------------------------------------
extern "C" void kernel_launch(void* const* d_in, const int* in_sizes, int n_in,
                              void* d_out, int out_size) {
    const float* in  = (const float*)d_in[0];
    const float* Wq  = (const float*)d_in[1];
    const float* bq  = (const float*)d_in[2];
    const float* Wk  = (const float*)d_in[3];
    const float* bk  = (const float*)d_in[4];
    const float* Wv  = (const float*)d_in[5];
    const float* bv  = (const float*)d_in[6];
    const float* Wo  = (const float*)d_in[7];
    const float* bo  = (const float*)d_in[8];
    const float* W1  = (const float*)d_in[9];
    const float* b1  = (const float*)d_in[10];
    const float* W2  = (const float*)d_in[11];
    const float* b2  = (const float*)d_in[12];
    const float* lng = (const float*)d_in[13];
    const float* lnb = (const float*)d_in[14];
    float* out = (float*)d_out;

    float *v, *pe;
    uint32_t *hnh, *hnl, *tmph, *tmpl, *ctxh, *ctxl;
    uint32_t *qh, *ql, *kh, *kl, *vh, *vl, *wh, *wl;
    cudaGetSymbolAddress((void**)&v,    g_v);
    cudaGetSymbolAddress((void**)&pe,   g_pe);
    cudaGetSymbolAddress((void**)&hnh,  g_hnh);
    cudaGetSymbolAddress((void**)&hnl,  g_hnl);
    cudaGetSymbolAddress((void**)&tmph, g_tmph);
    cudaGetSymbolAddress((void**)&tmpl, g_tmpl);
    cudaGetSymbolAddress((void**)&ctxh, g_ctxh);
    cudaGetSymbolAddress((void**)&ctxl, g_ctxl);
    cudaGetSymbolAddress((void**)&qh,   g_qh);
    cudaGetSymbolAddress((void**)&ql,   g_ql);
    cudaGetSymbolAddress((void**)&kh,   g_kh);
    cudaGetSymbolAddress((void**)&kl,   g_kl);
    cudaGetSymbolAddress((void**)&vh,   g_vh);
    cudaGetSymbolAddress((void**)&vl,   g_vl);
    cudaGetSymbolAddress((void**)&wh,   g_wh);
    cudaGetSymbolAddress((void**)&wl,   g_wl);

    cudaFuncSetAttribute(gemm_mma_kernel<5>, cudaFuncAttributeMaxDynamicSharedMemorySize, SMEM_G128);
    cudaFuncSetAttribute(gemm_mma_kernel<6>, cudaFuncAttributeMaxDynamicSharedMemorySize, SMEM_G128);
    cudaFuncSetAttribute(gemm_mma_kernel<7>, cudaFuncAttributeMaxDynamicSharedMemorySize, SMEM_G128);

    pe_kernel<<<128, 256>>>(pe);
    wsplit_kernel<<<dim3(64, 6), 256>>>(Wq, Wk, Wv, Wo, W1, W2, wh, wl);
    addpos_ln_kernel<<<ROWS / 8, 256>>>(in, pe, lng, lnb, hnh, hnl);

    for (int i = 0; i < NB; i++) {
        const uint32_t* Wqh = wh + (0 * NB + i) * 8192; const uint32_t* Wql = wl + (0 * NB + i) * 8192;
        const uint32_t* Wkh = wh + (1 * NB + i) * 8192; const uint32_t* Wkl = wl + (1 * NB + i) * 8192;
        const uint32_t* Wvh = wh + (2 * NB + i) * 8192; const uint32_t* Wvl = wl + (2 * NB + i) * 8192;
        const uint32_t* Woh = wh + (3 * NB + i) * 8192; const uint32_t* Wol = wl + (3 * NB + i) * 8192;
        const uint32_t* W1h = wh + (4 * NB + i) * 8192; const uint32_t* W1l = wl + (4 * NB + i) * 8192;
        const uint32_t* W2h = wh + (5 * NB + i) * 8192; const uint32_t* W2l = wl + (5 * NB + i) * 8192;
        const float* bqi = bq + i * DD;
        const float* bki = bk + i * DD;
        const float* bvi = bv + i * DD;
        const float* boi = bo + i * DD;
        const float* b1i = b1 + i * DD;
        const float* b2i = b2 + i * DD;

        qkv64_kernel<<<dim3(256, 3), 256>>>(hnh, hnl, Wqh, Wql, bqi, Wkh, Wkl, bki,
                                            Wvh, Wvl, bvi, qh, ql, kh, kl, v);
        vprep_kernel<<<512, 256>>>(v, vh, vl);
        attn_kernel<<<256, 256>>>(qh, ql, kh, kl, vh, vl, ctxh, ctxl);
        // Wo GEMM fused with pre-FFN LayerNorm -> split hn
        gemm_mma_kernel<5><<<256, 256, SMEM_G128>>>(ctxh, ctxl, Woh, Wol, boi,
                                                    nullptr, nullptr,
                                                    lng + (2 * i + 1) * DD, lnb + (2 * i + 1) * DD,
                                                    nullptr, hnh, hnl);
        // FFN inner (relu) -> split tmp  (N=64 tile, high occupancy)
        gemm64_kernel<1><<<256, 256>>>(hnh, hnl, W1h, W1l, b1i,
                                       nullptr, tmph, tmpl, 1.0f);
        // FFN outer + residual + next LN -> split hn, or final LN -> fp32 out
        if (i == NB - 1) {
            gemm_mma_kernel<7><<<256, 256, SMEM_G128>>>(tmph, tmpl, W2h, W2l, b2i,
                                                        hnh, hnl,
                                                        lng + 3 * DD, lnb + 3 * DD,
                                                        out, nullptr, nullptr);
        } else {
            gemm_mma_kernel<6><<<256, 256, SMEM_G128>>>(tmph, tmpl, W2h, W2l, b2i,
                                                        hnh, hnl,
                                                        lng + (2 * i + 2) * DD, lnb + (2 * i + 2) * DD,
                                                        nullptr, hnh, hnl);
        }
    }
}

// round 11
// speedup vs baseline: 1.1289x; 1.0782x over previous
#include <cuda_runtime.h>
#include <cuda_bf16.h>
#include <stdint.h>
#include <math.h>

#define NB 2
#define BB 4
#define TT 2048
#define DD 128
#define HH 4
#define DK 32
#define ROWS (BB*TT)          // 8192
#define LN_EPS 1e-3f
#define SMEM_G128 (128*36*16 + 1024)   // packed W tile (uint4) + LN reduction = 74752 B

// -------------------- scratch (device globals; no allocs allowed) ------------
__device__ float g_v  [ROWS*DD];
__device__ float g_pe [TT*DD];
// split activations, fragment-major widx layout: [row][64]
__device__ uint32_t g_hnh [ROWS*64], g_hnl [ROWS*64];
__device__ uint32_t g_tmph[ROWS*64], g_tmpl[ROWS*64];
__device__ uint32_t g_ctxh[ROWS*64], g_ctxl[ROWS*64];
// packed Q/K: [bh=16][t=2048][kc(2)*4+lr(4)] uint4 = {hi(dp),hi(dp+4),lo(dp),lo(dp+4)}
__device__ uint4 g_qp[32768*8];
__device__ uint4 g_kp[32768*8];
// packed V: [bh=16][tile(32)][d(32)][kc(4)*4+lr(4)] uint4 over key-pairs
__device__ uint4 g_vp[16*32*32*16];
// packed W: [matrix(12)][n(128)][kc(8)*4+lr(4)] uint4
__device__ uint4 g_wp[12*128*32];

// -------------------- split-bf16 helpers ---------------------------------------
__device__ __forceinline__ uint32_t pk_bf2(float a, float b) {
    __nv_bfloat162 t = __floats2bfloat162_rn(a, b);
    return *reinterpret_cast<uint32_t*>(&t);
}
__device__ __forceinline__ void split2(float a, float b, uint32_t& h, uint32_t& l) {
    float ah = __bfloat162float(__float2bfloat16(a));
    float bh = __bfloat162float(__float2bfloat16(b));
    h = pk_bf2(ah, bh);
    l = pk_bf2(a - ah, b - bh);
}
__device__ __forceinline__ float2 unsplit(uint32_t h, uint32_t l) {
    __nv_bfloat162 hb = *reinterpret_cast<__nv_bfloat162*>(&h);
    __nv_bfloat162 lb = *reinterpret_cast<__nv_bfloat162*>(&l);
    return make_float2(__bfloat162float(hb.x) + __bfloat162float(lb.x),
                       __bfloat162float(hb.y) + __bfloat162float(lb.y));
}
// fragment-major permutation for A-side activations
__device__ __forceinline__ int widx(int dp) {
    return (dp & ~7) + 2 * (dp & 3) + ((dp >> 2) & 1);
}
__device__ __forceinline__ void mma16816(float c[4], const uint32_t a[4], const uint32_t b[2]) {
    asm volatile(
        "mma.sync.aligned.m16n8k16.row.col.f32.bf16.bf16.f32 "
        "{%0,%1,%2,%3}, {%4,%5,%6,%7}, {%8,%9}, {%0,%1,%2,%3};\n"
        : "+f"(c[0]), "+f"(c[1]), "+f"(c[2]), "+f"(c[3])
        : "r"(a[0]), "r"(a[1]), "r"(a[2]), "r"(a[3]), "r"(b[0]), "r"(b[1]));
}

// -------------------- positional encoding -------------------------------------
__global__ void pe_kernel(float* __restrict__ pe) {
    int i = blockIdx.x;
    double f = exp(-((double)(2 * i) / 128.0) * 9.210340371976184);
    const double TWO_PI = 6.283185307179586;
    const double INV_TWO_PI = 0.15915494309189535;
    for (int t = threadIdx.x; t < TT; t += blockDim.x) {
        double ang = (double)t * f;
        double r = ang - TWO_PI * floor(ang * INV_TWO_PI);
        float rf = (float)r;
        pe[t * DD + i] = (i & 1) ? cosf(rf) : sinf(rf);
    }
}

// -------------------- fused addpos + first LayerNorm -> split hn -----------------
__global__ void addpos_ln_kernel(const float* __restrict__ in, const float* __restrict__ pe,
                                 const float* __restrict__ g, const float* __restrict__ b,
                                 uint32_t* __restrict__ Ch, uint32_t* __restrict__ Cl) {
    int row  = blockIdx.x * 8 + (threadIdx.x >> 5);
    int lane = threadIdx.x & 31;
    int t = row & (TT - 1);
    float4 xv = ((const float4*)in)[row * 32 + lane];
    float4 pv = ((const float4*)pe)[t * 32 + lane];
    xv.x += pv.x; xv.y += pv.y; xv.z += pv.z; xv.w += pv.w;
    float s = xv.x + xv.y + xv.z + xv.w;
    #pragma unroll
    for (int o = 16; o > 0; o >>= 1) s += __shfl_xor_sync(0xffffffff, s, o);
    float mu = s * (1.0f / 128.0f);
    float dx0 = xv.x - mu, dx1 = xv.y - mu, dx2 = xv.z - mu, dx3 = xv.w - mu;
    float sq = dx0*dx0 + dx1*dx1 + dx2*dx2 + dx3*dx3;
    #pragma unroll
    for (int o = 16; o > 0; o >>= 1) sq += __shfl_xor_sync(0xffffffff, sq, o);
    float var = sq * (1.0f / 128.0f);
    float r = rsqrtf(var + LN_EPS);
    float4 gv = ((const float4*)g)[lane];
    float4 bv = ((const float4*)b)[lane];
    float y0 = gv.x * dx0 * r + bv.x;
    float y1 = gv.y * dx1 * r + bv.y;
    float y2 = gv.z * dx2 * r + bv.z;
    float y3 = gv.w * dx3 * r + bv.w;
    uint32_t h0, l0, h1, l1;
    split2(y0, y1, h0, l0);
    split2(y2, y3, h1, l1);
    int base = row * 64;
    Ch[base + widx(2 * lane)]     = h0; Cl[base + widx(2 * lane)]     = l0;
    Ch[base + widx(2 * lane + 1)] = h1; Cl[base + widx(2 * lane + 1)] = l1;
}

// -------------------- weight pre-split into packed uint4 -------------------------
// Wp[(fam*NB+layer)][n][kc*4+lr] = {hi(kp=kc*8+lr), hi(kp+4), lo(kp), lo(kp+4)}
__global__ void wsplit_kernel(const float* __restrict__ Wq, const float* __restrict__ Wk,
                              const float* __restrict__ Wv, const float* __restrict__ Wo,
                              const float* __restrict__ W1, const float* __restrict__ W2,
                              uint4* __restrict__ wp) {
    const float* Ws[6] = {Wq, Wk, Wv, Wo, W1, W2};
    int fam = blockIdx.y;
    int idx = blockIdx.x * 256 + threadIdx.x;   // 0..8191 = NB*128*32
    int layer = idx >> 12;
    int rem = idx & 4095;
    int n = rem >> 5;
    int j = rem & 31;
    int kc = j >> 2, lr = j & 3;
    int kp1 = kc * 8 + lr, kp2 = kp1 + 4;
    const float* Wm = Ws[fam] + layer * 128 * 128;
    uint32_t h1, l1, h2, l2;
    split2(Wm[(2 * kp1) * 128 + n], Wm[(2 * kp1 + 1) * 128 + n], h1, l1);
    split2(Wm[(2 * kp2) * 128 + n], Wm[(2 * kp2 + 1) * 128 + n], h2, l2);
    wp[((fam * NB + layer) * 128 + n) * 32 + j] = make_uint4(h1, h2, l1, l2);
}

// -------------------- V transpose/split into packed uint4 ------------------------
// v fp32 [bh][t][32] -> Vp[bh][tile][d][kc*4+lr] = {hi(kp),hi(kp+4),lo(kp),lo(kp+4)}
__global__ void vprep_kernel(const float* __restrict__ v, uint4* __restrict__ vp) {
    __shared__ uint32_t sh[32][33];
    __shared__ uint32_t sl[32][33];
    int bh = blockIdx.x >> 5;
    int tile = blockIdx.x & 31;
    const float* vb = v + (size_t)bh * 2048 * 32 + (size_t)tile * 64 * 32;
    #pragma unroll
    for (int i = 0; i < 4; i++) {
        int idx = threadIdx.x + i * 256;   // 0..1023 = kp(32) x d(32)
        int kpl = idx >> 5;
        int d = idx & 31;
        float v0 = vb[(size_t)(2 * kpl) * 32 + d];
        float v1 = vb[(size_t)(2 * kpl + 1) * 32 + d];
        uint32_t hi, lo;
        split2(v0, v1, hi, lo);
        sh[d][kpl] = hi;
        sl[d][kpl] = lo;
    }
    __syncthreads();
    uint4* dst = vp + ((size_t)bh * 32 + tile) * 512;
    #pragma unroll
    for (int i = 0; i < 2; i++) {
        int idx = threadIdx.x + i * 256;   // 0..511 = d(32) x j(16)
        int d = idx >> 4;
        int j = idx & 15;
        int kc = j >> 2, lr = j & 3;
        int kp1 = kc * 8 + lr, kp2 = kp1 + 4;
        dst[d * 16 + j] = make_uint4(sh[d][kp1], sh[d][kp2], sl[d][kp1], sl[d][kp2]);
    }
}

// ==================== GEMM, N=64 tile: packed-W, split-A ========================
// block M=64 x N=64, 8 warps: rg=w>>1 rows, cg=w&1 cols.
// fused QKV: sel 0 -> packed Q (scaled), 1 -> packed K, 2 -> fp32 V scatter
__global__ __launch_bounds__(256) void qkv64_kernel(
        const uint32_t* __restrict__ Ah, const uint32_t* __restrict__ Al,
        const uint4* __restrict__ Wpq, const float* __restrict__ bq,
        const uint4* __restrict__ Wpk, const float* __restrict__ bk,
        const uint4* __restrict__ Wpv, const float* __restrict__ bv,
        uint4* __restrict__ qp, uint4* __restrict__ kp, float* __restrict__ v) {
    __shared__ __align__(16) uint4 Ws[64 * 36];
    int tid = threadIdx.x;
    int w = tid >> 5, lane = tid & 31;
    int lq = lane >> 2, lr = lane & 3;
    int rg = w >> 1, cg = w & 1;
    int m0 = (blockIdx.x >> 1) * 64;
    int n0 = (blockIdx.x & 1) * 64;
    int sel = blockIdx.y;
    const float QSCL = 0.17677669529663687f * 1.4426950408889634f;
    const uint4* Wp = (sel == 0) ? Wpq : (sel == 1) ? Wpk : Wpv;
    const float* bias = (sel == 0) ? bq : (sel == 1) ? bk : bv;
    float scl = (sel == 0) ? QSCL : 1.0f;

    #pragma unroll
    for (int i = 0; i < 8; i++) {
        int idx = tid + i * 256;            // 0..2047 uint4
        int n = idx >> 5, j = idx & 31;
        Ws[n * 36 + j] = Wp[(size_t)(n0 + n) * 32 + j];
    }

    int mrow = m0 + rg * 16 + lq;
    const uint32_t* Ah0 = Ah + (size_t)mrow * 64;
    const uint32_t* Al0 = Al + (size_t)mrow * 64;
    float acc[4][4] = {};
    __syncthreads();

    #pragma unroll
    for (int kc = 0; kc < 8; kc++) {
        int off = kc * 8 + 2 * lr;
        uint2 h0 = *(const uint2*)&Ah0[off];
        uint2 h1 = *(const uint2*)&Ah0[512 + off];
        uint2 lo0 = *(const uint2*)&Al0[off];
        uint2 lo1 = *(const uint2*)&Al0[512 + off];
        uint32_t ah[4] = { h0.x, h1.x, h0.y, h1.y };
        uint32_t al[4] = { lo0.x, lo1.x, lo0.y, lo1.y };
        #pragma unroll
        for (int nt = 0; nt < 4; nt++) {
            int n = cg * 32 + nt * 8 + lq;
            uint4 wv = Ws[n * 36 + kc * 4 + lr];
            uint32_t bh2[2] = { wv.x, wv.y };
            uint32_t bl2[2] = { wv.z, wv.w };
            mma16816(acc[nt], ah, bh2);
            mma16816(acc[nt], ah, bl2);
            mma16816(acc[nt], al, bh2);
        }
    }

    int hh = (n0 >> 5) + cg;            // global head 0..3
    int b0i = mrow >> 11, t0i = mrow & 2047;
    int b1i = (mrow + 8) >> 11, t1i = (mrow + 8) & 2047;
    if (sel == 2) {
        #pragma unroll
        for (int nt = 0; nt < 4; nt++) {
            int n = n0 + cg * 32 + nt * 8 + 2 * lr;
            float2 bv2 = *(const float2*)&bias[n];
            float2 o0 = { acc[nt][0] + bv2.x, acc[nt][1] + bv2.y };
            float2 o1 = { acc[nt][2] + bv2.x, acc[nt][3] + bv2.y };
            int dk = n & 31;
            *(float2*)&v[(((b0i << 2) + hh) * 2048 + t0i) * 32 + dk] = o0;
            *(float2*)&v[(((b1i << 2) + hh) * 2048 + t1i) * 32 + dk] = o1;
        }
    } else {
        uint4* Cp = (sel == 0) ? qp : kp;
        uint32_t hi0[4], lo0r[4], hi1[4], lo1r[4];
        #pragma unroll
        for (int nt = 0; nt < 4; nt++) {
            int n = n0 + cg * 32 + nt * 8 + 2 * lr;
            float2 bv2 = *(const float2*)&bias[n];
            split2((acc[nt][0] + bv2.x) * scl, (acc[nt][1] + bv2.y) * scl, hi0[nt], lo0r[nt]);
            split2((acc[nt][2] + bv2.x) * scl, (acc[nt][3] + bv2.y) * scl, hi1[nt], lo1r[nt]);
        }
        size_t base0 = ((size_t)((b0i << 2) + hh) * 2048 + t0i) * 8;
        size_t base1 = ((size_t)((b1i << 2) + hh) * 2048 + t1i) * 8;
        // kc=0: {nt0, nt1}, kc=1: {nt2, nt3}
        Cp[base0 + 0 * 4 + lr] = make_uint4(hi0[0], hi0[1], lo0r[0], lo0r[1]);
        Cp[base0 + 1 * 4 + lr] = make_uint4(hi0[2], hi0[3], lo0r[2], lo0r[3]);
        Cp[base1 + 0 * 4 + lr] = make_uint4(hi1[0], hi1[1], lo1r[0], lo1r[1]);
        Cp[base1 + 1 * 4 + lr] = make_uint4(hi1[2], hi1[3], lo1r[2], lo1r[3]);
    }
}

// plain N=64 GEMM, relu -> split widx output (FFN inner)
__global__ __launch_bounds__(256) void gemm64_relu_kernel(
        const uint32_t* __restrict__ Ah, const uint32_t* __restrict__ Al,
        const uint4* __restrict__ Wp, const float* __restrict__ bias,
        uint32_t* __restrict__ Ch, uint32_t* __restrict__ Cl) {
    __shared__ __align__(16) uint4 Ws[64 * 36];
    int tid = threadIdx.x;
    int w = tid >> 5, lane = tid & 31;
    int lq = lane >> 2, lr = lane & 3;
    int rg = w >> 1, cg = w & 1;
    int m0 = (blockIdx.x >> 1) * 64;
    int n0 = (blockIdx.x & 1) * 64;

    #pragma unroll
    for (int i = 0; i < 8; i++) {
        int idx = tid + i * 256;
        int n = idx >> 5, j = idx & 31;
        Ws[n * 36 + j] = Wp[(size_t)(n0 + n) * 32 + j];
    }

    int mrow = m0 + rg * 16 + lq;
    const uint32_t* Ah0 = Ah + (size_t)mrow * 64;
    const uint32_t* Al0 = Al + (size_t)mrow * 64;
    float acc[4][4] = {};
    __syncthreads();

    #pragma unroll
    for (int kc = 0; kc < 8; kc++) {
        int off = kc * 8 + 2 * lr;
        uint2 h0 = *(const uint2*)&Ah0[off];
        uint2 h1 = *(const uint2*)&Ah0[512 + off];
        uint2 lo0 = *(const uint2*)&Al0[off];
        uint2 lo1 = *(const uint2*)&Al0[512 + off];
        uint32_t ah[4] = { h0.x, h1.x, h0.y, h1.y };
        uint32_t al[4] = { lo0.x, lo1.x, lo0.y, lo1.y };
        #pragma unroll
        for (int nt = 0; nt < 4; nt++) {
            int n = cg * 32 + nt * 8 + lq;
            uint4 wv = Ws[n * 36 + kc * 4 + lr];
            uint32_t bh2[2] = { wv.x, wv.y };
            uint32_t bl2[2] = { wv.z, wv.w };
            mma16816(acc[nt], ah, bh2);
            mma16816(acc[nt], ah, bl2);
            mma16816(acc[nt], al, bh2);
        }
    }

    #pragma unroll
    for (int nt = 0; nt < 4; nt++) {
        int n = n0 + cg * 32 + nt * 8 + 2 * lr;
        float2 bv = *(const float2*)&bias[n];
        float o00 = fmaxf(acc[nt][0] + bv.x, 0.f);
        float o01 = fmaxf(acc[nt][1] + bv.y, 0.f);
        float o10 = fmaxf(acc[nt][2] + bv.x, 0.f);
        float o11 = fmaxf(acc[nt][3] + bv.y, 0.f);
        int wi = widx(n >> 1);
        uint32_t hi, lo;
        split2(o00, o01, hi, lo);
        Ch[(size_t)mrow * 64 + wi] = hi; Cl[(size_t)mrow * 64 + wi] = lo;
        split2(o10, o11, hi, lo);
        Ch[(size_t)(mrow + 8) * 64 + wi] = hi; Cl[(size_t)(mrow + 8) * 64 + wi] = lo;
    }
}

// ==================== GEMM, N=128 tile (LN modes 5/6/7) ==========================
template <int MODE>
__global__ __launch_bounds__(256) void gemm_mma_kernel(
        const uint32_t* __restrict__ Ah, const uint32_t* __restrict__ Al,
        const uint4* __restrict__ Wp, const float* __restrict__ bias,
        const uint32_t* __restrict__ Rh, const uint32_t* __restrict__ Rl,
        const float* __restrict__ lng, const float* __restrict__ lnb,
        float* __restrict__ C, uint32_t* __restrict__ Ch, uint32_t* __restrict__ Cl) {
    extern __shared__ uint32_t dyn[];
    uint4 (*Ws) = (uint4*)dyn;
    float (*ssum)[4] = (float(*)[4])(dyn + 128 * 36 * 4);
    float (*ssq)[4]  = (float(*)[4])(dyn + 128 * 36 * 4 + 128);
    int tid = threadIdx.x;
    int w = tid >> 5, lane = tid & 31;
    int lq = lane >> 2, lr = lane & 3;
    int rg = w >> 2, cg = w & 3;
    int m0 = blockIdx.x * 32;

    #pragma unroll
    for (int i = 0; i < 16; i++) {
        int idx = tid + i * 256;            // 0..4095 uint4
        int n = idx >> 5, j = idx & 31;
        Ws[n * 36 + j] = Wp[(size_t)n * 32 + j];
    }

    int mrow = m0 + rg * 16 + lq;
    const uint32_t* Ah0 = Ah + (size_t)mrow * 64;
    const uint32_t* Al0 = Al + (size_t)mrow * 64;
    float acc[4][4] = {};
    __syncthreads();

    #pragma unroll
    for (int kc = 0; kc < 8; kc++) {
        int off = kc * 8 + 2 * lr;
        uint2 h0 = *(const uint2*)&Ah0[off];
        uint2 h1 = *(const uint2*)&Ah0[512 + off];
        uint2 lo0 = *(const uint2*)&Al0[off];
        uint2 lo1 = *(const uint2*)&Al0[512 + off];
        uint32_t ah[4] = { h0.x, h1.x, h0.y, h1.y };
        uint32_t al[4] = { lo0.x, lo1.x, lo0.y, lo1.y };
        #pragma unroll
        for (int nt = 0; nt < 4; nt++) {
            int n = cg * 32 + nt * 8 + lq;
            uint4 wv = Ws[n * 36 + kc * 4 + lr];
            uint32_t bh2[2] = { wv.x, wv.y };
            uint32_t bl2[2] = { wv.z, wv.w };
            mma16816(acc[nt], ah, bh2);
            mma16816(acc[nt], ah, bl2);
            mma16816(acc[nt], al, bh2);
        }
    }

    float xs[4][4];
    #pragma unroll
    for (int nt = 0; nt < 4; nt++) {
        int n = cg * 32 + nt * 8 + 2 * lr;
        float2 bv = *(const float2*)&bias[n];
        xs[nt][0] = acc[nt][0] + bv.x;
        xs[nt][1] = acc[nt][1] + bv.y;
        xs[nt][2] = acc[nt][2] + bv.x;
        xs[nt][3] = acc[nt][3] + bv.y;
        if (MODE == 6 || MODE == 7) {
            int wi = widx(cg * 16 + nt * 4 + lr);
            float2 r0 = unsplit(Rh[(size_t)mrow * 64 + wi], Rl[(size_t)mrow * 64 + wi]);
            float2 r1 = unsplit(Rh[(size_t)(mrow + 8) * 64 + wi], Rl[(size_t)(mrow + 8) * 64 + wi]);
            xs[nt][0] += r0.x; xs[nt][1] += r0.y;
            xs[nt][2] += r1.x; xs[nt][3] += r1.y;
        }
    }
    float sA = 0, qA = 0, sB = 0, qB = 0;
    #pragma unroll
    for (int nt = 0; nt < 4; nt++) {
        sA += xs[nt][0] + xs[nt][1];
        qA += xs[nt][0]*xs[nt][0] + xs[nt][1]*xs[nt][1];
        sB += xs[nt][2] + xs[nt][3];
        qB += xs[nt][2]*xs[nt][2] + xs[nt][3]*xs[nt][3];
    }
    #pragma unroll
    for (int o2 = 1; o2 < 4; o2 <<= 1) {
        sA += __shfl_xor_sync(0xffffffff, sA, o2);
        qA += __shfl_xor_sync(0xffffffff, qA, o2);
        sB += __shfl_xor_sync(0xffffffff, sB, o2);
        qB += __shfl_xor_sync(0xffffffff, qB, o2);
    }
    int ra = rg * 16 + lq, rb = ra + 8;
    if (lr == 0) {
        ssum[ra][cg] = sA; ssq[ra][cg] = qA;
        ssum[rb][cg] = sB; ssq[rb][cg] = qB;
    }
    __syncthreads();
    float fsA = ssum[ra][0] + ssum[ra][1] + ssum[ra][2] + ssum[ra][3];
    float fqA = ssq[ra][0] + ssq[ra][1] + ssq[ra][2] + ssq[ra][3];
    float fsB = ssum[rb][0] + ssum[rb][1] + ssum[rb][2] + ssum[rb][3];
    float fqB = ssq[rb][0] + ssq[rb][1] + ssq[rb][2] + ssq[rb][3];
    float muA = fsA * (1.0f / 128.0f);
    float muB = fsB * (1.0f / 128.0f);
    float rA = rsqrtf(fqA * (1.0f / 128.0f) - muA * muA + LN_EPS);
    float rB = rsqrtf(fqB * (1.0f / 128.0f) - muB * muB + LN_EPS);
    #pragma unroll
    for (int nt = 0; nt < 4; nt++) {
        int n = cg * 32 + nt * 8 + 2 * lr;
        float2 gv  = *(const float2*)&lng[n];
        float2 bv2 = *(const float2*)&lnb[n];
        float y00 = gv.x * (xs[nt][0] - muA) * rA + bv2.x;
        float y01 = gv.y * (xs[nt][1] - muA) * rA + bv2.y;
        float y10 = gv.x * (xs[nt][2] - muB) * rB + bv2.x;
        float y11 = gv.y * (xs[nt][3] - muB) * rB + bv2.y;
        if (MODE == 7) {
            *(float2*)&C[(size_t)mrow * 128 + n] = make_float2(y00, y01);
            *(float2*)&C[(size_t)(mrow + 8) * 128 + n] = make_float2(y10, y11);
        } else {
            int wi = widx(cg * 16 + nt * 4 + lr);
            uint32_t hi, lo;
            split2(y00, y01, hi, lo);
            Ch[(size_t)mrow * 64 + wi] = hi; Cl[(size_t)mrow * 64 + wi] = lo;
            split2(y10, y11, hi, lo);
            Ch[(size_t)(mrow + 8) * 64 + wi] = hi; Cl[(size_t)(mrow + 8) * 64 + wi] = lo;
        }
    }
}

// -------------------- flash attention (packed-uint4 K/V, LDS.128 frags) ----------
__global__ __launch_bounds__(256) void attn_kernel(
        const uint4* __restrict__ Qp, const uint4* __restrict__ Kp,
        const uint4* __restrict__ Vp,
        uint32_t* __restrict__ Ch, uint32_t* __restrict__ Cl) {
    __shared__ __align__(16) uint4 Ks[2][64 * 12];   // stride 12 uint4 (mod 8 = 4)
    __shared__ __align__(16) uint4 Vs[2][32 * 20];   // stride 20 uint4 (mod 8 = 4)

    int bid = blockIdx.x;
    int bh  = bid >> 4;
    int qc  = bid & 15;
    int q0  = qc * 128;
    int tid = threadIdx.x;
    int w    = tid >> 5;
    int lane = tid & 31;
    int lq   = lane >> 2;
    int lr   = lane & 3;
    int row0 = q0 + w * 16 + lq;

    const uint4* QpB = Qp + (size_t)bh * 2048 * 8;
    const uint4* KpB = Kp + (size_t)bh * 2048 * 8;
    const uint4* VpB = Vp + (size_t)bh * 32 * 512;

    uint32_t qh[2][4], ql[2][4];
    #pragma unroll
    for (int c2 = 0; c2 < 2; c2++) {
        uint4 a0 = QpB[(size_t)row0 * 8 + c2 * 4 + lr];
        uint4 a1 = QpB[(size_t)(row0 + 8) * 8 + c2 * 4 + lr];
        qh[c2][0] = a0.x; qh[c2][1] = a1.x; qh[c2][2] = a0.y; qh[c2][3] = a1.y;
        ql[c2][0] = a0.z; ql[c2][1] = a1.z; ql[c2][2] = a0.w; ql[c2][3] = a1.w;
    }

    float m0 = -1e30f, m1 = -1e30f, l0 = 0.f, l1 = 0.f;
    float o[4][4] = {};

    int kkey = tid >> 3, kj = tid & 7;       // K: key 0..31 (+32 on p=1), j 0..7
    int vd = tid >> 4, vj = tid & 15;        // V: d 0..15 (+16 on p=1), j 0..15
    uint4 kr[2], vr[2];
    kr[0] = KpB[(size_t)kkey * 8 + kj];
    kr[1] = KpB[(size_t)(kkey + 32) * 8 + kj];
    vr[0] = VpB[(size_t)vd * 16 + vj];
    vr[1] = VpB[(size_t)(vd + 16) * 16 + vj];

    for (int tile = 0; tile < 32; tile++) {
        int cur = tile & 1;
        Ks[cur][kkey * 12 + kj] = kr[0];
        Ks[cur][(kkey + 32) * 12 + kj] = kr[1];
        Vs[cur][vd * 20 + vj] = vr[0];
        Vs[cur][(vd + 16) * 20 + vj] = vr[1];

        if (tile < 31) {
            size_t kt = (size_t)(tile + 1) * 64;
            size_t vt = (size_t)(tile + 1) * 512;
            kr[0] = KpB[(kt + kkey) * 8 + kj];
            kr[1] = KpB[(kt + kkey + 32) * 8 + kj];
            vr[0] = VpB[vt + (size_t)vd * 16 + vj];
            vr[1] = VpB[vt + (size_t)(vd + 16) * 16 + vj];
        }
        __syncthreads();

        // ---- QK^T (log2 domain; Q pre-scaled) ----
        float c[8][4] = {};
        #pragma unroll
        for (int nt = 0; nt < 8; nt++) {
            int key = nt * 8 + lq;
            #pragma unroll
            for (int kc = 0; kc < 2; kc++) {
                uint4 kv = Ks[cur][key * 12 + kc * 4 + lr];
                uint32_t bhf[2] = { kv.x, kv.y };
                uint32_t blf[2] = { kv.z, kv.w };
                mma16816(c[nt], qh[kc], bhf);
                mma16816(c[nt], qh[kc], blf);
                mma16816(c[nt], ql[kc], bhf);
            }
        }

        // ---- online softmax (base 2) ----
        float mx0 = -1e30f, mx1 = -1e30f;
        #pragma unroll
        for (int nt = 0; nt < 8; nt++) {
            mx0 = fmaxf(mx0, fmaxf(c[nt][0], c[nt][1]));
            mx1 = fmaxf(mx1, fmaxf(c[nt][2], c[nt][3]));
        }
        mx0 = fmaxf(mx0, __shfl_xor_sync(0xffffffff, mx0, 1));
        mx0 = fmaxf(mx0, __shfl_xor_sync(0xffffffff, mx0, 2));
        mx1 = fmaxf(mx1, __shfl_xor_sync(0xffffffff, mx1, 1));
        mx1 = fmaxf(mx1, __shfl_xor_sync(0xffffffff, mx1, 2));
        float nm0 = fmaxf(m0, mx0), nm1 = fmaxf(m1, mx1);
        float f0 = exp2f(m0 - nm0), f1 = exp2f(m1 - nm1);
        m0 = nm0; m1 = nm1;
        l0 *= f0; l1 *= f1;
        #pragma unroll
        for (int dt = 0; dt < 4; dt++) {
            o[dt][0] *= f0; o[dt][1] *= f0;
            o[dt][2] *= f1; o[dt][3] *= f1;
        }
        #pragma unroll
        for (int nt = 0; nt < 8; nt++) {
            c[nt][0] = exp2f(c[nt][0] - m0);
            c[nt][1] = exp2f(c[nt][1] - m0);
            c[nt][2] = exp2f(c[nt][2] - m1);
            c[nt][3] = exp2f(c[nt][3] - m1);
            l0 += c[nt][0] + c[nt][1];
            l1 += c[nt][2] + c[nt][3];
        }

        // ---- P @ V ----
        #pragma unroll
        for (int kc = 0; kc < 4; kc++) {
            uint32_t ah[4], al[4];
            split2(c[2*kc][0],   c[2*kc][1],   ah[0], al[0]);
            split2(c[2*kc][2],   c[2*kc][3],   ah[1], al[1]);
            split2(c[2*kc+1][0], c[2*kc+1][1], ah[2], al[2]);
            split2(c[2*kc+1][2], c[2*kc+1][3], ah[3], al[3]);
            #pragma unroll
            for (int dt = 0; dt < 4; dt++) {
                int d = dt * 8 + lq;
                uint4 vv = Vs[cur][d * 20 + kc * 4 + lr];
                uint32_t bhf[2] = { vv.x, vv.y };
                uint32_t blf[2] = { vv.z, vv.w };
                mma16816(o[dt], ah, bhf);
                mma16816(o[dt], ah, blf);
                mma16816(o[dt], al, bhf);
            }
        }
    }

    // ---- epilogue: split ctx (widx layout) ----
    l0 += __shfl_xor_sync(0xffffffff, l0, 1);
    l0 += __shfl_xor_sync(0xffffffff, l0, 2);
    l1 += __shfl_xor_sync(0xffffffff, l1, 1);
    l1 += __shfl_xor_sync(0xffffffff, l1, 2);
    float inv0 = 1.0f / l0, inv1 = 1.0f / l1;
    int b = bh >> 2, hh = bh & 3;
    size_t r0 = (size_t)(b * TT + row0) * 64;
    size_t r1 = (size_t)(b * TT + row0 + 8) * 64;
    #pragma unroll
    for (int dt = 0; dt < 4; dt++) {
        int wi = widx(hh * 16 + dt * 4 + lr);
        uint32_t hi, lo;
        split2(o[dt][0] * inv0, o[dt][1] * inv0, hi, lo);
        Ch[r0 + wi] = hi; Cl[r0 + wi] = lo;
        split2(o[dt][2] * inv1, o[dt][3] * inv1, hi, lo);
        Ch[r1 + wi] = hi; Cl[r1 + wi] = lo;
    }
}

// -------------------- launch ------------------------------------------------------
extern "C" void kernel_launch(void* const* d_in, const int* in_sizes, int n_in,
                              void* d_out, int out_size) {
    const float* in  = (const float*)d_in[0];
    const float* Wq  = (const float*)d_in[1];
    const float* bq  = (const float*)d_in[2];
    const float* Wk  = (const float*)d_in[3];
    const float* bk  = (const float*)d_in[4];
    const float* Wv  = (const float*)d_in[5];
    const float* bv  = (const float*)d_in[6];
    const float* Wo  = (const float*)d_in[7];
    const float* bo  = (const float*)d_in[8];
    const float* W1  = (const float*)d_in[9];
    const float* b1  = (const float*)d_in[10];
    const float* W2  = (const float*)d_in[11];
    const float* b2  = (const float*)d_in[12];
    const float* lng = (const float*)d_in[13];
    const float* lnb = (const float*)d_in[14];
    float* out = (float*)d_out;

    float *v, *pe;
    uint32_t *hnh, *hnl, *tmph, *tmpl, *ctxh, *ctxl;
    uint4 *qp, *kp, *vp, *wp;
    cudaGetSymbolAddress((void**)&v,    g_v);
    cudaGetSymbolAddress((void**)&pe,   g_pe);
    cudaGetSymbolAddress((void**)&hnh,  g_hnh);
    cudaGetSymbolAddress((void**)&hnl,  g_hnl);
    cudaGetSymbolAddress((void**)&tmph, g_tmph);
    cudaGetSymbolAddress((void**)&tmpl, g_tmpl);
    cudaGetSymbolAddress((void**)&ctxh, g_ctxh);
    cudaGetSymbolAddress((void**)&ctxl, g_ctxl);
    cudaGetSymbolAddress((void**)&qp,   g_qp);
    cudaGetSymbolAddress((void**)&kp,   g_kp);
    cudaGetSymbolAddress((void**)&vp,   g_vp);
    cudaGetSymbolAddress((void**)&wp,   g_wp);

    cudaFuncSetAttribute(gemm_mma_kernel<5>, cudaFuncAttributeMaxDynamicSharedMemorySize, SMEM_G128);
    cudaFuncSetAttribute(gemm_mma_kernel<6>, cudaFuncAttributeMaxDynamicSharedMemorySize, SMEM_G128);
    cudaFuncSetAttribute(gemm_mma_kernel<7>, cudaFuncAttributeMaxDynamicSharedMemorySize, SMEM_G128);

    pe_kernel<<<128, 256>>>(pe);
    wsplit_kernel<<<dim3(32, 6), 256>>>(Wq, Wk, Wv, Wo, W1, W2, wp);
    addpos_ln_kernel<<<ROWS / 8, 256>>>(in, pe, lng, lnb, hnh, hnl);

    for (int i = 0; i < NB; i++) {
        const uint4* Wpq = wp + (size_t)(0 * NB + i) * 4096;
        const uint4* Wpk = wp + (size_t)(1 * NB + i) * 4096;
        const uint4* Wpv = wp + (size_t)(2 * NB + i) * 4096;
        const uint4* Wpo = wp + (size_t)(3 * NB + i) * 4096;
        const uint4* Wp1 = wp + (size_t)(4 * NB + i) * 4096;
        const uint4* Wp2 = wp + (size_t)(5 * NB + i) * 4096;
        const float* bqi = bq + i * DD;
        const float* bki = bk + i * DD;
        const float* bvi = bv + i * DD;
        const float* boi = bo + i * DD;
        const float* b1i = b1 + i * DD;
        const float* b2i = b2 + i * DD;

        qkv64_kernel<<<dim3(256, 3), 256>>>(hnh, hnl, Wpq, bqi, Wpk, bki, Wpv, bvi,
                                            qp, kp, v);
        vprep_kernel<<<512, 256>>>(v, vp);
        attn_kernel<<<256, 256>>>(qp, kp, vp, ctxh, ctxl);
        // Wo GEMM fused with pre-FFN LayerNorm -> split hn
        gemm_mma_kernel<5><<<256, 256, SMEM_G128>>>(ctxh, ctxl, Wpo, boi,
                                                    nullptr, nullptr,
                                                    lng + (2 * i + 1) * DD, lnb + (2 * i + 1) * DD,
                                                    nullptr, hnh, hnl);
        // FFN inner (relu) -> split tmp
        gemm64_relu_kernel<<<256, 256>>>(hnh, hnl, Wp1, b1i, tmph, tmpl);
        // FFN outer + residual + next LN -> split hn, or final LN -> fp32 out
        if (i == NB - 1) {
            gemm_mma_kernel<7><<<256, 256, SMEM_G128>>>(tmph, tmpl, Wp2, b2i,
                                                        hnh, hnl,
                                                        lng + 3 * DD, lnb + 3 * DD,
                                                        out, nullptr, nullptr);
        } else {
            gemm_mma_kernel<6><<<256, 256, SMEM_G128>>>(tmph, tmpl, Wp2, b2i,
                                                        hnh, hnl,
                                                        lng + (2 * i + 2) * DD, lnb + (2 * i + 2) * DD,
                                                        nullptr, hnh, hnl);
        }
    }
}

// round 12
// speedup vs baseline: 1.2077x; 1.0698x over previous
#include <cuda_runtime.h>
#include <cuda_bf16.h>
#include <stdint.h>
#include <math.h>

#define NB 2
#define BB 4
#define TT 2048
#define DD 128
#define HH 4
#define DK 32
#define ROWS (BB*TT)          // 8192
#define LN_EPS 1e-3f
#define SMEM_G128 (128*36*16 + 1024)   // packed W tile (uint4) + LN reduction = 74752 B

// -------------------- scratch (device globals; no allocs allowed) ------------
__device__ float g_pe [TT*DD];
// packed activations: [row][kc(8)*4+lr(4)] uint4 = {hi(dp),hi(dp+4),lo(dp),lo(dp+4)}
__device__ uint4 g_hnp [ROWS*32];
__device__ uint4 g_tmpp[ROWS*32];
__device__ uint4 g_ctxp[ROWS*32];
// packed Q/K: [bh=16][t=2048][kc(2)*4+lr(4)]
__device__ uint4 g_qp[32768*8];
__device__ uint4 g_kp[32768*8];
// packed V: [bh=16][tile(32)][d(32)][kc(4)*4+lr(4)] over key-pairs
__device__ uint4 g_vp[16*32*32*16];
// packed W: [matrix(12)][n(128)][kc(8)*4+lr(4)]
__device__ uint4 g_wp[12*128*32];

// -------------------- split-bf16 helpers ---------------------------------------
__device__ __forceinline__ uint32_t pk_bf2(float a, float b) {
    __nv_bfloat162 t = __floats2bfloat162_rn(a, b);
    return *reinterpret_cast<uint32_t*>(&t);
}
__device__ __forceinline__ void split2(float a, float b, uint32_t& h, uint32_t& l) {
    float ah = __bfloat162float(__float2bfloat16(a));
    float bh = __bfloat162float(__float2bfloat16(b));
    h = pk_bf2(ah, bh);
    l = pk_bf2(a - ah, b - bh);
}
__device__ __forceinline__ float2 unsplit(uint32_t h, uint32_t l) {
    __nv_bfloat162 hb = *reinterpret_cast<__nv_bfloat162*>(&h);
    __nv_bfloat162 lb = *reinterpret_cast<__nv_bfloat162*>(&l);
    return make_float2(__bfloat162float(hb.x) + __bfloat162float(lb.x),
                       __bfloat162float(hb.y) + __bfloat162float(lb.y));
}
__device__ __forceinline__ void mma16816(float c[4], const uint32_t a[4], const uint32_t b[2]) {
    asm volatile(
        "mma.sync.aligned.m16n8k16.row.col.f32.bf16.bf16.f32 "
        "{%0,%1,%2,%3}, {%4,%5,%6,%7}, {%8,%9}, {%0,%1,%2,%3};\n"
        : "+f"(c[0]), "+f"(c[1]), "+f"(c[2]), "+f"(c[3])
        : "r"(a[0]), "r"(a[1]), "r"(a[2]), "r"(a[3]), "r"(b[0]), "r"(b[1]));
}

// -------------------- positional encoding -------------------------------------
__global__ void pe_kernel(float* __restrict__ pe) {
    int i = blockIdx.x;
    double f = exp(-((double)(2 * i) / 128.0) * 9.210340371976184);
    const double TWO_PI = 6.283185307179586;
    const double INV_TWO_PI = 0.15915494309189535;
    for (int t = threadIdx.x; t < TT; t += blockDim.x) {
        double ang = (double)t * f;
        double r = ang - TWO_PI * floor(ang * INV_TWO_PI);
        float rf = (float)r;
        pe[t * DD + i] = (i & 1) ? cosf(rf) : sinf(rf);
    }
}

// -------------------- fused addpos + first LayerNorm -> packed hn ----------------
// one warp per row; lane j owns dp = (j>>2)*8 + (j&3), d = {2dp,2dp+1,2dp+8,2dp+9}
__global__ void addpos_ln_kernel(const float* __restrict__ in, const float* __restrict__ pe,
                                 const float* __restrict__ g, const float* __restrict__ b,
                                 uint4* __restrict__ Cp) {
    int row  = blockIdx.x * 8 + (threadIdx.x >> 5);
    int j    = threadIdx.x & 31;
    int dp   = ((j >> 2) << 3) + (j & 3);
    int d0   = 2 * dp;
    int t = row & (TT - 1);
    const float* inr = in + (size_t)row * 128;
    const float* per = pe + (size_t)t * 128;
    float2 xa = *(const float2*)&inr[d0];
    float2 xb = *(const float2*)&inr[d0 + 8];
    float2 pa = *(const float2*)&per[d0];
    float2 pb = *(const float2*)&per[d0 + 8];
    xa.x += pa.x; xa.y += pa.y; xb.x += pb.x; xb.y += pb.y;
    float s = xa.x + xa.y + xb.x + xb.y;
    #pragma unroll
    for (int o = 16; o > 0; o >>= 1) s += __shfl_xor_sync(0xffffffff, s, o);
    float mu = s * (1.0f / 128.0f);
    float dx0 = xa.x - mu, dx1 = xa.y - mu, dx2 = xb.x - mu, dx3 = xb.y - mu;
    float sq = dx0*dx0 + dx1*dx1 + dx2*dx2 + dx3*dx3;
    #pragma unroll
    for (int o = 16; o > 0; o >>= 1) sq += __shfl_xor_sync(0xffffffff, sq, o);
    float var = sq * (1.0f / 128.0f);
    float r = rsqrtf(var + LN_EPS);
    float2 ga = *(const float2*)&g[d0];
    float2 gb = *(const float2*)&g[d0 + 8];
    float2 ba = *(const float2*)&b[d0];
    float2 bb = *(const float2*)&b[d0 + 8];
    float y0 = ga.x * dx0 * r + ba.x;
    float y1 = ga.y * dx1 * r + ba.y;
    float y2 = gb.x * dx2 * r + bb.x;
    float y3 = gb.y * dx3 * r + bb.y;
    uint32_t h0, l0, h1, l1;
    split2(y0, y1, h0, l0);
    split2(y2, y3, h1, l1);
    Cp[(size_t)row * 32 + j] = make_uint4(h0, h1, l0, l1);
}

// -------------------- weight pre-split into packed uint4 -------------------------
__global__ void wsplit_kernel(const float* __restrict__ Wq, const float* __restrict__ Wk,
                              const float* __restrict__ Wv, const float* __restrict__ Wo,
                              const float* __restrict__ W1, const float* __restrict__ W2,
                              uint4* __restrict__ wp) {
    const float* Ws[6] = {Wq, Wk, Wv, Wo, W1, W2};
    int fam = blockIdx.y;
    int idx = blockIdx.x * 256 + threadIdx.x;   // 0..8191 = NB*128*32
    int layer = idx >> 12;
    int rem = idx & 4095;
    int n = rem >> 5;
    int j = rem & 31;
    int kc = j >> 2, lr = j & 3;
    int kp1 = kc * 8 + lr, kp2 = kp1 + 4;
    const float* Wm = Ws[fam] + layer * 128 * 128;
    uint32_t h1, l1, h2, l2;
    split2(Wm[(2 * kp1) * 128 + n], Wm[(2 * kp1 + 1) * 128 + n], h1, l1);
    split2(Wm[(2 * kp2) * 128 + n], Wm[(2 * kp2 + 1) * 128 + n], h2, l2);
    wp[((fam * NB + layer) * 128 + n) * 32 + j] = make_uint4(h1, h2, l1, l2);
}

// ==================== fused QKV (N=64 tile), V-path writes packed Vp ==============
__global__ __launch_bounds__(256) void qkv64_kernel(
        const uint4* __restrict__ Ap,
        const uint4* __restrict__ Wpq, const float* __restrict__ bq,
        const uint4* __restrict__ Wpk, const float* __restrict__ bk,
        const uint4* __restrict__ Wpv, const float* __restrict__ bv,
        uint4* __restrict__ qp, uint4* __restrict__ kp, uint4* __restrict__ vp) {
    __shared__ __align__(16) uint4 Ws[64 * 36];
    int tid = threadIdx.x;
    int w = tid >> 5, lane = tid & 31;
    int lq = lane >> 2, lr = lane & 3;
    int rg = w >> 1, cg = w & 1;
    int m0 = (blockIdx.x >> 1) * 64;
    int n0 = (blockIdx.x & 1) * 64;
    int sel = blockIdx.y;
    const float QSCL = 0.17677669529663687f * 1.4426950408889634f;
    const uint4* Wp = (sel == 0) ? Wpq : (sel == 1) ? Wpk : Wpv;
    const float* bias = (sel == 0) ? bq : (sel == 1) ? bk : bv;
    float scl = (sel == 0) ? QSCL : 1.0f;

    #pragma unroll
    for (int i = 0; i < 8; i++) {
        int idx = tid + i * 256;
        int n = idx >> 5, j = idx & 31;
        Ws[n * 36 + j] = Wp[(size_t)(n0 + n) * 32 + j];
    }

    int mrow = m0 + rg * 16 + lq;
    const uint4* A0 = Ap + (size_t)mrow * 32;
    const uint4* A1 = Ap + (size_t)(mrow + 8) * 32;
    float acc[4][4] = {};
    __syncthreads();

    #pragma unroll
    for (int kc = 0; kc < 8; kc++) {
        uint4 a0 = A0[kc * 4 + lr];
        uint4 a1 = A1[kc * 4 + lr];
        uint32_t ah[4] = { a0.x, a1.x, a0.y, a1.y };
        uint32_t al[4] = { a0.z, a1.z, a0.w, a1.w };
        #pragma unroll
        for (int nt = 0; nt < 4; nt++) {
            int n = cg * 32 + nt * 8 + lq;
            uint4 wv = Ws[n * 36 + kc * 4 + lr];
            uint32_t bh2[2] = { wv.x, wv.y };
            uint32_t bl2[2] = { wv.z, wv.w };
            mma16816(acc[nt], ah, bh2);
            mma16816(acc[nt], ah, bl2);
            mma16816(acc[nt], al, bh2);
        }
    }

    if (sel == 2) {
        // V path: transpose + split into packed Vp via smem (reuse Ws)
        float* Vt = (float*)Ws;              // 64 dcol x 65 stride floats (16.6 KB)
        __syncthreads();                     // mainloop smem reads done
        int k0 = rg * 16 + lq;               // local key 0..15 (+8)
        #pragma unroll
        for (int nt = 0; nt < 4; nt++) {
            int dc = cg * 32 + nt * 8 + 2 * lr;
            int n = n0 + dc;
            float2 bv2 = *(const float2*)&bias[n];
            Vt[dc * 65 + k0]           = acc[nt][0] + bv2.x;
            Vt[(dc + 1) * 65 + k0]     = acc[nt][1] + bv2.y;
            Vt[dc * 65 + k0 + 8]       = acc[nt][2] + bv2.x;
            Vt[(dc + 1) * 65 + k0 + 8] = acc[nt][3] + bv2.y;
        }
        __syncthreads();
        int b = m0 >> 11, tile = (m0 & 2047) >> 6;
        #pragma unroll
        for (int i = 0; i < 4; i++) {
            int idx = tid + i * 256;         // 0..1023 = dcol(64) x j(16)
            int dc = idx >> 4, j = idx & 15;
            int kc2 = j >> 2, lr2 = j & 3;
            int kpi = kc2 * 8 + lr2;
            float v0 = Vt[dc * 65 + 2 * kpi];
            float v1 = Vt[dc * 65 + 2 * kpi + 1];
            float v2 = Vt[dc * 65 + 2 * kpi + 8];
            float v3 = Vt[dc * 65 + 2 * kpi + 9];
            uint32_t h1, l1, h2, l2;
            split2(v0, v1, h1, l1);
            split2(v2, v3, h2, l2);
            int bh = (b << 2) + (n0 >> 5) + (dc >> 5);
            int d = dc & 31;
            vp[(((size_t)bh * 32 + tile) * 32 + d) * 16 + j] = make_uint4(h1, h2, l1, l2);
        }
        return;
    }

    // Q/K path: packed scatter [bh][t][8]
    uint4* Cp = (sel == 0) ? qp : kp;
    int hh = (n0 >> 5) + cg;
    int b0i = mrow >> 11, t0i = mrow & 2047;
    int b1i = (mrow + 8) >> 11, t1i = (mrow + 8) & 2047;
    uint32_t hi0[4], lo0r[4], hi1[4], lo1r[4];
    #pragma unroll
    for (int nt = 0; nt < 4; nt++) {
        int n = n0 + cg * 32 + nt * 8 + 2 * lr;
        float2 bv2 = *(const float2*)&bias[n];
        split2((acc[nt][0] + bv2.x) * scl, (acc[nt][1] + bv2.y) * scl, hi0[nt], lo0r[nt]);
        split2((acc[nt][2] + bv2.x) * scl, (acc[nt][3] + bv2.y) * scl, hi1[nt], lo1r[nt]);
    }
    size_t base0 = ((size_t)((b0i << 2) + hh) * 2048 + t0i) * 8;
    size_t base1 = ((size_t)((b1i << 2) + hh) * 2048 + t1i) * 8;
    Cp[base0 + lr]     = make_uint4(hi0[0], hi0[1], lo0r[0], lo0r[1]);
    Cp[base0 + 4 + lr] = make_uint4(hi0[2], hi0[3], lo0r[2], lo0r[3]);
    Cp[base1 + lr]     = make_uint4(hi1[0], hi1[1], lo1r[0], lo1r[1]);
    Cp[base1 + 4 + lr] = make_uint4(hi1[2], hi1[3], lo1r[2], lo1r[3]);
}

// ==================== N=64 GEMM, relu -> packed output (FFN inner) ================
__global__ __launch_bounds__(256) void gemm64_relu_kernel(
        const uint4* __restrict__ Ap, const uint4* __restrict__ Wp,
        const float* __restrict__ bias, uint4* __restrict__ Cp) {
    __shared__ __align__(16) uint4 Ws[64 * 36];
    int tid = threadIdx.x;
    int w = tid >> 5, lane = tid & 31;
    int lq = lane >> 2, lr = lane & 3;
    int rg = w >> 1, cg = w & 1;
    int m0 = (blockIdx.x >> 1) * 64;
    int n0 = (blockIdx.x & 1) * 64;

    #pragma unroll
    for (int i = 0; i < 8; i++) {
        int idx = tid + i * 256;
        int n = idx >> 5, j = idx & 31;
        Ws[n * 36 + j] = Wp[(size_t)(n0 + n) * 32 + j];
    }

    int mrow = m0 + rg * 16 + lq;
    const uint4* A0 = Ap + (size_t)mrow * 32;
    const uint4* A1 = Ap + (size_t)(mrow + 8) * 32;
    float acc[4][4] = {};
    __syncthreads();

    #pragma unroll
    for (int kc = 0; kc < 8; kc++) {
        uint4 a0 = A0[kc * 4 + lr];
        uint4 a1 = A1[kc * 4 + lr];
        uint32_t ah[4] = { a0.x, a1.x, a0.y, a1.y };
        uint32_t al[4] = { a0.z, a1.z, a0.w, a1.w };
        #pragma unroll
        for (int nt = 0; nt < 4; nt++) {
            int n = cg * 32 + nt * 8 + lq;
            uint4 wv = Ws[n * 36 + kc * 4 + lr];
            uint32_t bh2[2] = { wv.x, wv.y };
            uint32_t bl2[2] = { wv.z, wv.w };
            mma16816(acc[nt], ah, bh2);
            mma16816(acc[nt], ah, bl2);
            mma16816(acc[nt], al, bh2);
        }
    }

    uint32_t h0[4], l0a[4], h1a[4], l1a[4];
    #pragma unroll
    for (int nt = 0; nt < 4; nt++) {
        int n = n0 + cg * 32 + nt * 8 + 2 * lr;
        float2 bv = *(const float2*)&bias[n];
        split2(fmaxf(acc[nt][0] + bv.x, 0.f), fmaxf(acc[nt][1] + bv.y, 0.f), h0[nt], l0a[nt]);
        split2(fmaxf(acc[nt][2] + bv.x, 0.f), fmaxf(acc[nt][3] + bv.y, 0.f), h1a[nt], l1a[nt]);
    }
    int jb = (n0 >> 2) + cg * 8 + lr;   // n0/4 + cg*8 + lr
    Cp[(size_t)mrow * 32 + jb]           = make_uint4(h0[0], h0[1], l0a[0], l0a[1]);
    Cp[(size_t)mrow * 32 + jb + 4]       = make_uint4(h0[2], h0[3], l0a[2], l0a[3]);
    Cp[(size_t)(mrow + 8) * 32 + jb]     = make_uint4(h1a[0], h1a[1], l1a[0], l1a[1]);
    Cp[(size_t)(mrow + 8) * 32 + jb + 4] = make_uint4(h1a[2], h1a[3], l1a[2], l1a[3]);
}

// ==================== N=128 GEMM + LN (modes 5/6/7) ===============================
// MODE 5: LN(acc+bias) -> packed; 6: LN(acc+bias+R) -> packed; 7: same -> fp32 C
template <int MODE>
__global__ __launch_bounds__(256) void gemm_mma_kernel(
        const uint4* __restrict__ Ap, const uint4* __restrict__ Wp,
        const float* __restrict__ bias, const uint4* __restrict__ Rp,
        const float* __restrict__ lng, const float* __restrict__ lnb,
        float* __restrict__ C, uint4* __restrict__ Cp) {
    extern __shared__ uint32_t dyn[];
    uint4* Ws = (uint4*)dyn;
    float (*ssum)[4] = (float(*)[4])(dyn + 128 * 36 * 4);
    float (*ssq)[4]  = (float(*)[4])(dyn + 128 * 36 * 4 + 128);
    int tid = threadIdx.x;
    int w = tid >> 5, lane = tid & 31;
    int lq = lane >> 2, lr = lane & 3;
    int rg = w >> 2, cg = w & 3;
    int m0 = blockIdx.x * 32;

    #pragma unroll
    for (int i = 0; i < 16; i++) {
        int idx = tid + i * 256;
        int n = idx >> 5, j = idx & 31;
        Ws[n * 36 + j] = Wp[(size_t)n * 32 + j];
    }

    int mrow = m0 + rg * 16 + lq;
    const uint4* A0 = Ap + (size_t)mrow * 32;
    const uint4* A1 = Ap + (size_t)(mrow + 8) * 32;
    float acc[4][4] = {};
    __syncthreads();

    #pragma unroll
    for (int kc = 0; kc < 8; kc++) {
        uint4 a0 = A0[kc * 4 + lr];
        uint4 a1 = A1[kc * 4 + lr];
        uint32_t ah[4] = { a0.x, a1.x, a0.y, a1.y };
        uint32_t al[4] = { a0.z, a1.z, a0.w, a1.w };
        #pragma unroll
        for (int nt = 0; nt < 4; nt++) {
            int n = cg * 32 + nt * 8 + lq;
            uint4 wv = Ws[n * 36 + kc * 4 + lr];
            uint32_t bh2[2] = { wv.x, wv.y };
            uint32_t bl2[2] = { wv.z, wv.w };
            mma16816(acc[nt], ah, bh2);
            mma16816(acc[nt], ah, bl2);
            mma16816(acc[nt], al, bh2);
        }
    }

    float xs[4][4];
    if (MODE == 6 || MODE == 7) {
        uint4 rA0 = Rp[(size_t)mrow * 32 + cg * 8 + lr];
        uint4 rA1 = Rp[(size_t)mrow * 32 + cg * 8 + 4 + lr];
        uint4 rB0 = Rp[(size_t)(mrow + 8) * 32 + cg * 8 + lr];
        uint4 rB1 = Rp[(size_t)(mrow + 8) * 32 + cg * 8 + 4 + lr];
        float2 r;
        r = unsplit(rA0.x, rA0.z); xs[0][0] = r.x; xs[0][1] = r.y;
        r = unsplit(rA0.y, rA0.w); xs[1][0] = r.x; xs[1][1] = r.y;
        r = unsplit(rA1.x, rA1.z); xs[2][0] = r.x; xs[2][1] = r.y;
        r = unsplit(rA1.y, rA1.w); xs[3][0] = r.x; xs[3][1] = r.y;
        r = unsplit(rB0.x, rB0.z); xs[0][2] = r.x; xs[0][3] = r.y;
        r = unsplit(rB0.y, rB0.w); xs[1][2] = r.x; xs[1][3] = r.y;
        r = unsplit(rB1.x, rB1.z); xs[2][2] = r.x; xs[2][3] = r.y;
        r = unsplit(rB1.y, rB1.w); xs[3][2] = r.x; xs[3][3] = r.y;
    } else {
        #pragma unroll
        for (int nt = 0; nt < 4; nt++)
            xs[nt][0] = xs[nt][1] = xs[nt][2] = xs[nt][3] = 0.f;
    }
    #pragma unroll
    for (int nt = 0; nt < 4; nt++) {
        int n = cg * 32 + nt * 8 + 2 * lr;
        float2 bv = *(const float2*)&bias[n];
        xs[nt][0] += acc[nt][0] + bv.x;
        xs[nt][1] += acc[nt][1] + bv.y;
        xs[nt][2] += acc[nt][2] + bv.x;
        xs[nt][3] += acc[nt][3] + bv.y;
    }
    float sA = 0, qA = 0, sB = 0, qB = 0;
    #pragma unroll
    for (int nt = 0; nt < 4; nt++) {
        sA += xs[nt][0] + xs[nt][1];
        qA += xs[nt][0]*xs[nt][0] + xs[nt][1]*xs[nt][1];
        sB += xs[nt][2] + xs[nt][3];
        qB += xs[nt][2]*xs[nt][2] + xs[nt][3]*xs[nt][3];
    }
    #pragma unroll
    for (int o2 = 1; o2 < 4; o2 <<= 1) {
        sA += __shfl_xor_sync(0xffffffff, sA, o2);
        qA += __shfl_xor_sync(0xffffffff, qA, o2);
        sB += __shfl_xor_sync(0xffffffff, sB, o2);
        qB += __shfl_xor_sync(0xffffffff, qB, o2);
    }
    int ra = rg * 16 + lq, rb = ra + 8;
    if (lr == 0) {
        ssum[ra][cg] = sA; ssq[ra][cg] = qA;
        ssum[rb][cg] = sB; ssq[rb][cg] = qB;
    }
    __syncthreads();
    float fsA = ssum[ra][0] + ssum[ra][1] + ssum[ra][2] + ssum[ra][3];
    float fqA = ssq[ra][0] + ssq[ra][1] + ssq[ra][2] + ssq[ra][3];
    float fsB = ssum[rb][0] + ssum[rb][1] + ssum[rb][2] + ssum[rb][3];
    float fqB = ssq[rb][0] + ssq[rb][1] + ssq[rb][2] + ssq[rb][3];
    float muA = fsA * (1.0f / 128.0f);
    float muB = fsB * (1.0f / 128.0f);
    float rA = rsqrtf(fqA * (1.0f / 128.0f) - muA * muA + LN_EPS);
    float rB = rsqrtf(fqB * (1.0f / 128.0f) - muB * muB + LN_EPS);
    float yA[4][2], yB[4][2];
    #pragma unroll
    for (int nt = 0; nt < 4; nt++) {
        int n = cg * 32 + nt * 8 + 2 * lr;
        float2 gv  = *(const float2*)&lng[n];
        float2 bv2 = *(const float2*)&lnb[n];
        yA[nt][0] = gv.x * (xs[nt][0] - muA) * rA + bv2.x;
        yA[nt][1] = gv.y * (xs[nt][1] - muA) * rA + bv2.y;
        yB[nt][0] = gv.x * (xs[nt][2] - muB) * rB + bv2.x;
        yB[nt][1] = gv.y * (xs[nt][3] - muB) * rB + bv2.y;
    }
    if (MODE == 7) {
        #pragma unroll
        for (int nt = 0; nt < 4; nt++) {
            int n = cg * 32 + nt * 8 + 2 * lr;
            *(float2*)&C[(size_t)mrow * 128 + n] = make_float2(yA[nt][0], yA[nt][1]);
            *(float2*)&C[(size_t)(mrow + 8) * 128 + n] = make_float2(yB[nt][0], yB[nt][1]);
        }
    } else {
        uint32_t hA[4], lA[4], hB[4], lB[4];
        #pragma unroll
        for (int nt = 0; nt < 4; nt++) {
            split2(yA[nt][0], yA[nt][1], hA[nt], lA[nt]);
            split2(yB[nt][0], yB[nt][1], hB[nt], lB[nt]);
        }
        int jb = cg * 8 + lr;
        Cp[(size_t)mrow * 32 + jb]           = make_uint4(hA[0], hA[1], lA[0], lA[1]);
        Cp[(size_t)mrow * 32 + jb + 4]       = make_uint4(hA[2], hA[3], lA[2], lA[3]);
        Cp[(size_t)(mrow + 8) * 32 + jb]     = make_uint4(hB[0], hB[1], lB[0], lB[1]);
        Cp[(size_t)(mrow + 8) * 32 + jb + 4] = make_uint4(hB[2], hB[3], lB[2], lB[3]);
    }
}

// -------------------- flash attention (packed uint4 everywhere) ------------------
__global__ __launch_bounds__(256) void attn_kernel(
        const uint4* __restrict__ Qp, const uint4* __restrict__ Kp,
        const uint4* __restrict__ Vp, uint4* __restrict__ Cp) {
    __shared__ __align__(16) uint4 Ks[2][64 * 12];
    __shared__ __align__(16) uint4 Vs[2][32 * 20];

    int bid = blockIdx.x;
    int bh  = bid >> 4;
    int qc  = bid & 15;
    int q0  = qc * 128;
    int tid = threadIdx.x;
    int w    = tid >> 5;
    int lane = tid & 31;
    int lq   = lane >> 2;
    int lr   = lane & 3;
    int row0 = q0 + w * 16 + lq;

    const uint4* QpB = Qp + (size_t)bh * 2048 * 8;
    const uint4* KpB = Kp + (size_t)bh * 2048 * 8;
    const uint4* VpB = Vp + (size_t)bh * 32 * 512;

    uint32_t qh[2][4], ql[2][4];
    #pragma unroll
    for (int c2 = 0; c2 < 2; c2++) {
        uint4 a0 = QpB[(size_t)row0 * 8 + c2 * 4 + lr];
        uint4 a1 = QpB[(size_t)(row0 + 8) * 8 + c2 * 4 + lr];
        qh[c2][0] = a0.x; qh[c2][1] = a1.x; qh[c2][2] = a0.y; qh[c2][3] = a1.y;
        ql[c2][0] = a0.z; ql[c2][1] = a1.z; ql[c2][2] = a0.w; ql[c2][3] = a1.w;
    }

    float m0 = -1e30f, m1 = -1e30f, l0 = 0.f, l1 = 0.f;
    float o[4][4] = {};

    int kkey = tid >> 3, kj = tid & 7;
    int vd = tid >> 4, vj = tid & 15;
    uint4 kr[2], vr[2];
    kr[0] = KpB[(size_t)kkey * 8 + kj];
    kr[1] = KpB[(size_t)(kkey + 32) * 8 + kj];
    vr[0] = VpB[(size_t)vd * 16 + vj];
    vr[1] = VpB[(size_t)(vd + 16) * 16 + vj];

    for (int tile = 0; tile < 32; tile++) {
        int cur = tile & 1;
        Ks[cur][kkey * 12 + kj] = kr[0];
        Ks[cur][(kkey + 32) * 12 + kj] = kr[1];
        Vs[cur][vd * 20 + vj] = vr[0];
        Vs[cur][(vd + 16) * 20 + vj] = vr[1];

        if (tile < 31) {
            size_t kt = (size_t)(tile + 1) * 64;
            size_t vt = (size_t)(tile + 1) * 512;
            kr[0] = KpB[(kt + kkey) * 8 + kj];
            kr[1] = KpB[(kt + kkey + 32) * 8 + kj];
            vr[0] = VpB[vt + (size_t)vd * 16 + vj];
            vr[1] = VpB[vt + (size_t)(vd + 16) * 16 + vj];
        }
        __syncthreads();

        float c[8][4] = {};
        #pragma unroll
        for (int nt = 0; nt < 8; nt++) {
            int key = nt * 8 + lq;
            #pragma unroll
            for (int kc = 0; kc < 2; kc++) {
                uint4 kv = Ks[cur][key * 12 + kc * 4 + lr];
                uint32_t bhf[2] = { kv.x, kv.y };
                uint32_t blf[2] = { kv.z, kv.w };
                mma16816(c[nt], qh[kc], bhf);
                mma16816(c[nt], qh[kc], blf);
                mma16816(c[nt], ql[kc], bhf);
            }
        }

        float mx0 = -1e30f, mx1 = -1e30f;
        #pragma unroll
        for (int nt = 0; nt < 8; nt++) {
            mx0 = fmaxf(mx0, fmaxf(c[nt][0], c[nt][1]));
            mx1 = fmaxf(mx1, fmaxf(c[nt][2], c[nt][3]));
        }
        mx0 = fmaxf(mx0, __shfl_xor_sync(0xffffffff, mx0, 1));
        mx0 = fmaxf(mx0, __shfl_xor_sync(0xffffffff, mx0, 2));
        mx1 = fmaxf(mx1, __shfl_xor_sync(0xffffffff, mx1, 1));
        mx1 = fmaxf(mx1, __shfl_xor_sync(0xffffffff, mx1, 2));
        float nm0 = fmaxf(m0, mx0), nm1 = fmaxf(m1, mx1);
        float f0 = exp2f(m0 - nm0), f1 = exp2f(m1 - nm1);
        m0 = nm0; m1 = nm1;
        l0 *= f0; l1 *= f1;
        #pragma unroll
        for (int dt = 0; dt < 4; dt++) {
            o[dt][0] *= f0; o[dt][1] *= f0;
            o[dt][2] *= f1; o[dt][3] *= f1;
        }
        #pragma unroll
        for (int nt = 0; nt < 8; nt++) {
            c[nt][0] = exp2f(c[nt][0] - m0);
            c[nt][1] = exp2f(c[nt][1] - m0);
            c[nt][2] = exp2f(c[nt][2] - m1);
            c[nt][3] = exp2f(c[nt][3] - m1);
            l0 += c[nt][0] + c[nt][1];
            l1 += c[nt][2] + c[nt][3];
        }

        #pragma unroll
        for (int kc = 0; kc < 4; kc++) {
            uint32_t ah[4], al[4];
            split2(c[2*kc][0],   c[2*kc][1],   ah[0], al[0]);
            split2(c[2*kc][2],   c[2*kc][3],   ah[1], al[1]);
            split2(c[2*kc+1][0], c[2*kc+1][1], ah[2], al[2]);
            split2(c[2*kc+1][2], c[2*kc+1][3], ah[3], al[3]);
            #pragma unroll
            for (int dt = 0; dt < 4; dt++) {
                int d = dt * 8 + lq;
                uint4 vv = Vs[cur][d * 20 + kc * 4 + lr];
                uint32_t bhf[2] = { vv.x, vv.y };
                uint32_t blf[2] = { vv.z, vv.w };
                mma16816(o[dt], ah, bhf);
                mma16816(o[dt], ah, blf);
                mma16816(o[dt], al, bhf);
            }
        }
    }

    // epilogue: packed ctx
    l0 += __shfl_xor_sync(0xffffffff, l0, 1);
    l0 += __shfl_xor_sync(0xffffffff, l0, 2);
    l1 += __shfl_xor_sync(0xffffffff, l1, 1);
    l1 += __shfl_xor_sync(0xffffffff, l1, 2);
    float inv0 = 1.0f / l0, inv1 = 1.0f / l1;
    int b = bh >> 2, hh = bh & 3;
    size_t r0 = (size_t)(b * TT + row0) * 32;
    size_t r1 = (size_t)(b * TT + row0 + 8) * 32;
    uint32_t h0[4], l0a[4], h1[4], l1a[4];
    #pragma unroll
    for (int dt = 0; dt < 4; dt++) {
        split2(o[dt][0] * inv0, o[dt][1] * inv0, h0[dt], l0a[dt]);
        split2(o[dt][2] * inv1, o[dt][3] * inv1, h1[dt], l1a[dt]);
    }
    Cp[r0 + hh * 8 + lr]     = make_uint4(h0[0], h0[1], l0a[0], l0a[1]);
    Cp[r0 + hh * 8 + 4 + lr] = make_uint4(h0[2], h0[3], l0a[2], l0a[3]);
    Cp[r1 + hh * 8 + lr]     = make_uint4(h1[0], h1[1], l1a[0], l1a[1]);
    Cp[r1 + hh * 8 + 4 + lr] = make_uint4(h1[2], h1[3], l1a[2], l1a[3]);
}

// -------------------- launch ------------------------------------------------------
extern "C" void kernel_launch(void* const* d_in, const int* in_sizes, int n_in,
                              void* d_out, int out_size) {
    const float* in  = (const float*)d_in[0];
    const float* Wq  = (const float*)d_in[1];
    const float* bq  = (const float*)d_in[2];
    const float* Wk  = (const float*)d_in[3];
    const float* bk  = (const float*)d_in[4];
    const float* Wv  = (const float*)d_in[5];
    const float* bv  = (const float*)d_in[6];
    const float* Wo  = (const float*)d_in[7];
    const float* bo  = (const float*)d_in[8];
    const float* W1  = (const float*)d_in[9];
    const float* b1  = (const float*)d_in[10];
    const float* W2  = (const float*)d_in[11];
    const float* b2  = (const float*)d_in[12];
    const float* lng = (const float*)d_in[13];
    const float* lnb = (const float*)d_in[14];
    float* out = (float*)d_out;

    float* pe;
    uint4 *hnp, *tmpp, *ctxp, *qp, *kp, *vp, *wp;
    cudaGetSymbolAddress((void**)&pe,   g_pe);
    cudaGetSymbolAddress((void**)&hnp,  g_hnp);
    cudaGetSymbolAddress((void**)&tmpp, g_tmpp);
    cudaGetSymbolAddress((void**)&ctxp, g_ctxp);
    cudaGetSymbolAddress((void**)&qp,   g_qp);
    cudaGetSymbolAddress((void**)&kp,   g_kp);
    cudaGetSymbolAddress((void**)&vp,   g_vp);
    cudaGetSymbolAddress((void**)&wp,   g_wp);

    cudaFuncSetAttribute(gemm_mma_kernel<5>, cudaFuncAttributeMaxDynamicSharedMemorySize, SMEM_G128);
    cudaFuncSetAttribute(gemm_mma_kernel<6>, cudaFuncAttributeMaxDynamicSharedMemorySize, SMEM_G128);
    cudaFuncSetAttribute(gemm_mma_kernel<7>, cudaFuncAttributeMaxDynamicSharedMemorySize, SMEM_G128);

    pe_kernel<<<128, 256>>>(pe);
    wsplit_kernel<<<dim3(32, 6), 256>>>(Wq, Wk, Wv, Wo, W1, W2, wp);
    addpos_ln_kernel<<<ROWS / 8, 256>>>(in, pe, lng, lnb, hnp);

    for (int i = 0; i < NB; i++) {
        const uint4* Wpq = wp + (size_t)(0 * NB + i) * 4096;
        const uint4* Wpk = wp + (size_t)(1 * NB + i) * 4096;
        const uint4* Wpv = wp + (size_t)(2 * NB + i) * 4096;
        const uint4* Wpo = wp + (size_t)(3 * NB + i) * 4096;
        const uint4* Wp1 = wp + (size_t)(4 * NB + i) * 4096;
        const uint4* Wp2 = wp + (size_t)(5 * NB + i) * 4096;
        const float* bqi = bq + i * DD;
        const float* bki = bk + i * DD;
        const float* bvi = bv + i * DD;
        const float* boi = bo + i * DD;
        const float* b1i = b1 + i * DD;
        const float* b2i = b2 + i * DD;

        qkv64_kernel<<<dim3(256, 3), 256>>>(hnp, Wpq, bqi, Wpk, bki, Wpv, bvi,
                                            qp, kp, vp);
        attn_kernel<<<256, 256>>>(qp, kp, vp, ctxp);
        gemm_mma_kernel<5><<<256, 256, SMEM_G128>>>(ctxp, Wpo, boi, nullptr,
                                                    lng + (2 * i + 1) * DD, lnb + (2 * i + 1) * DD,
                                                    nullptr, hnp);
        gemm64_relu_kernel<<<256, 256>>>(hnp, Wp1, b1i, tmpp);
        if (i == NB - 1) {
            gemm_mma_kernel<7><<<256, 256, SMEM_G128>>>(tmpp, Wp2, b2i, hnp,
                                                        lng + 3 * DD, lnb + 3 * DD,
                                                        out, nullptr);
        } else {
            gemm_mma_kernel<6><<<256, 256, SMEM_G128>>>(tmpp, Wp2, b2i, hnp,
                                                        lng + (2 * i + 2) * DD, lnb + (2 * i + 2) * DD,
                                                        nullptr, hnp);
        }
    }
}